// round 1
// baseline (speedup 1.0000x reference)
#include <cuda_runtime.h>
#include <stdint.h>

#define N_NODES  50000
#define N_EDGES  1600000
#define IN_F     128
#define OUT_F    128
#define HEADS    4
#define HEAD_DIM 32
#define NEG_SLOPE 0.2f

// ---------------- device scratch (no allocations allowed) ----------------
__device__ float g_h[N_NODES * OUT_F];      // transformed features (25.6 MB)
__device__ float g_as[N_NODES * HEADS];     // alpha_src partial per node/head
__device__ float g_ad[N_NODES * HEADS];     // alpha_dst partial per node/head
__device__ int   g_is64;                    // edge_index dtype flag

// ---------------- dtype detection for edge_index -------------------------
// If the data is int64 (values < 2^31), every odd 32-bit word of the first
// 128 packed values is zero. For genuine int32 random indices in [0,50000)
// that pattern has probability ~0.
__global__ void detect_kernel(const int* __restrict__ ei) {
    if (threadIdx.x == 0 && blockIdx.x == 0) {
        int allzero = 1;
        #pragma unroll 1
        for (int i = 1; i < 256; i += 2) {
            if (ei[i] != 0) { allzero = 0; break; }
        }
        g_is64 = allzero;
    }
}

// ---------------- zero the output ----------------------------------------
__global__ void zero_kernel(float4* __restrict__ out, int n4) {
    int i = blockIdx.x * blockDim.x + threadIdx.x;
    if (i < n4) out[i] = make_float4(0.f, 0.f, 0.f, 0.f);
}

// ---------------- GEMM h = x @ W^T, fused alpha epilogue -----------------
// Block: 128 threads (one per output column). Each block computes ROWS rows.
// W is staged in smem transposed in two 64-k halves (padded to kill bank
// conflicts). Warp w == head w, so the alpha dot products reduce with shfl.
#define ROWS 16
__global__ __launch_bounds__(128) void gemm_alpha_kernel(
    const float* __restrict__ x,
    const float* __restrict__ W,
    const float* __restrict__ a)
{
    __shared__ float xs[ROWS][IN_F];
    __shared__ float Ws[64][129];        // Ws[k][c] = W[c][kbase+k], padded

    const int t = threadIdx.x;           // output column 0..127
    const int rowbase = blockIdx.x * ROWS;   // 3125 * 16 == 50000 exactly

    // stage x rows (coalesced)
    for (int i = t; i < ROWS * IN_F; i += 128)
        xs[i >> 7][i & 127] = x[(rowbase + (i >> 7)) * IN_F + (i & 127)];

    float acc[ROWS];
    #pragma unroll
    for (int r = 0; r < ROWS; r++) acc[r] = 0.f;

    for (int half = 0; half < 2; half++) {
        const int kbase = half * 64;
        __syncthreads();
        // stage W half, transposed into smem
        for (int j = t; j < 128 * 64; j += 128) {
            int c  = j >> 6;
            int kk = j & 63;
            Ws[kk][c] = W[c * IN_F + kbase + kk];
        }
        __syncthreads();

        #pragma unroll
        for (int k = 0; k < 64; k += 4) {
            float w0 = Ws[k    ][t];
            float w1 = Ws[k + 1][t];
            float w2 = Ws[k + 2][t];
            float w3 = Ws[k + 3][t];
            #pragma unroll
            for (int r = 0; r < ROWS; r++) {
                float4 xv = *(const float4*)&xs[r][kbase + k];
                acc[r] = fmaf(xv.x, w0, acc[r]);
                acc[r] = fmaf(xv.y, w1, acc[r]);
                acc[r] = fmaf(xv.z, w2, acc[r]);
                acc[r] = fmaf(xv.w, w3, acc[r]);
            }
        }
    }

    // epilogue: write h, reduce alpha_src/alpha_dst per (row, head)
    const int head = t >> 5;     // warp id == head id
    const int d    = t & 31;
    const float av_s = a[head * 2 * HEAD_DIM + d];
    const float av_d = a[head * 2 * HEAD_DIM + HEAD_DIM + d];
    const unsigned mask = 0xffffffffu;

    #pragma unroll
    for (int r = 0; r < ROWS; r++) {
        const int row = rowbase + r;
        g_h[row * OUT_F + t] = acc[r];
        float s  = acc[r] * av_s;
        float dd = acc[r] * av_d;
        #pragma unroll
        for (int off = 16; off > 0; off >>= 1) {
            s  += __shfl_down_sync(mask, s,  off);
            dd += __shfl_down_sync(mask, dd, off);
        }
        if (d == 0) {
            g_as[row * HEADS + head] = s;
            g_ad[row * HEADS + head] = dd;
        }
    }
}

// ---------------- edge scatter: one warp per edge ------------------------
__global__ __launch_bounds__(256) void edge_kernel(
    const int* __restrict__ ei32, float* __restrict__ out)
{
    const int warp = (blockIdx.x * blockDim.x + threadIdx.x) >> 5;
    const int lane = threadIdx.x & 31;
    if (warp >= N_EDGES) return;

    int src, dst;
    if (g_is64) {
        const long long* ei = (const long long*)ei32;
        src = (int)__ldg(&ei[warp]);
        dst = (int)__ldg(&ei[N_EDGES + warp]);
    } else {
        src = __ldg(&ei32[warp]);
        dst = __ldg(&ei32[N_EDGES + warp]);
    }

    // attention coefficient per head, computed in lanes 0..3, broadcast
    float v = 0.f;
    if (lane < HEADS) {
        float s = g_as[src * HEADS + lane] + g_ad[dst * HEADS + lane];
        v = (s > 0.f) ? s : NEG_SLOPE * s;
    }
    const float att = __shfl_sync(0xffffffffu, v, lane >> 3);

    // each lane owns 4 consecutive floats of the 128-wide feature row
    float4 hv = *(const float4*)&g_h[src * OUT_F + lane * 4];
    float4 m;
    m.x = att * hv.x; m.y = att * hv.y; m.z = att * hv.z; m.w = att * hv.w;

    float* p = &out[dst * OUT_F + lane * 4];
    asm volatile("red.global.add.v4.f32 [%0], {%1,%2,%3,%4};"
                 :: "l"(p), "f"(m.x), "f"(m.y), "f"(m.z), "f"(m.w)
                 : "memory");
}

// ---------------- launch -------------------------------------------------
extern "C" void kernel_launch(void* const* d_in, const int* in_sizes, int n_in,
                              void* d_out, int out_size) {
    const float* x  = (const float*)d_in[0];
    const int*   ei = (const int*)d_in[1];   // int32 or int64 (detected on device)
    const float* W  = (const float*)d_in[2];
    const float* a  = (const float*)d_in[3];
    float* out = (float*)d_out;

    detect_kernel<<<1, 32>>>(ei);

    const int n4 = N_NODES * OUT_F / 4;
    zero_kernel<<<(n4 + 255) / 256, 256>>>((float4*)out, n4);

    gemm_alpha_kernel<<<N_NODES / ROWS, 128>>>(x, W, a);

    const int warps_per_block = 256 / 32;
    const int blocks = (N_EDGES + warps_per_block - 1) / warps_per_block;
    edge_kernel<<<blocks, 256>>>(ei, out);
}

// round 3
// speedup vs baseline: 1.1611x; 1.1611x over previous
#include <cuda_runtime.h>
#include <stdint.h>

#define N_NODES  50000
#define N_EDGES  1600000
#define IN_F     128
#define OUT_F    128
#define HEADS    4
#define HEAD_DIM 32
#define NEG_SLOPE 0.2f

// ---------------- device scratch (no allocations allowed) ----------------
__device__ float g_h [N_NODES * OUT_F];     // transformed features (25.6 MB)
__device__ float g_as[N_NODES * HEADS];     // alpha_src per node/head
__device__ float g_ad[N_NODES * HEADS];     // alpha_dst per node/head
__device__ int   g_cnt[N_NODES];            // in-degree histogram
__device__ int   g_off[N_NODES + 1];        // CSR row offsets (by dst)
__device__ int   g_cur[N_NODES];            // scatter cursors
__device__ int   g_srcs[N_EDGES];           // src index, sorted by dst
__device__ int   g_is64;                    // edge_index dtype flag

// ---------------- dtype detection for edge_index -------------------------
__global__ void detect_kernel(const int* __restrict__ ei) {
    if (threadIdx.x == 0 && blockIdx.x == 0) {
        int allzero = 1;
        #pragma unroll 1
        for (int i = 1; i < 256; i += 2) {
            if (ei[i] != 0) { allzero = 0; break; }
        }
        g_is64 = allzero;
    }
}

// ---------------- zero the histogram --------------------------------------
__global__ void zero_cnt_kernel() {
    int i = blockIdx.x * blockDim.x + threadIdx.x;
    if (i < N_NODES) g_cnt[i] = 0;
}

// ---------------- histogram of dst ----------------------------------------
__global__ __launch_bounds__(256) void hist_kernel(const int* __restrict__ ei32) {
    int e = blockIdx.x * blockDim.x + threadIdx.x;
    if (e >= N_EDGES) return;
    int dst;
    if (g_is64) dst = (int)((const long long*)ei32)[N_EDGES + e];
    else        dst = ei32[N_EDGES + e];
    atomicAdd(&g_cnt[dst], 1);
}

// ---------------- single-CTA exclusive scan (two-pass over g_cnt) --------
__global__ __launch_bounds__(1024) void scan_kernel() {
    __shared__ int sm[1024];
    const int CH = (N_NODES + 1023) / 1024;     // 49
    const int t = threadIdx.x;
    const int base = t * CH;

    int sum = 0;
    #pragma unroll 1
    for (int i = 0; i < CH; i++) {
        int idx = base + i;
        if (idx < N_NODES) sum += g_cnt[idx];
    }
    sm[t] = sum;
    __syncthreads();
    // inclusive Hillis-Steele scan over 1024 partials
    #pragma unroll 1
    for (int off = 1; off < 1024; off <<= 1) {
        int v = (t >= off) ? sm[t - off] : 0;
        __syncthreads();
        sm[t] += v;
        __syncthreads();
    }
    int run = (t == 0) ? 0 : sm[t - 1];
    #pragma unroll 1
    for (int i = 0; i < CH; i++) {
        int idx = base + i;
        if (idx < N_NODES) {
            g_off[idx] = run;
            g_cur[idx] = run;
            run += g_cnt[idx];
        }
    }
    if (t == 0) g_off[N_NODES] = sm[1023];
}

// ---------------- scatter srcs into dst-sorted order ----------------------
__global__ __launch_bounds__(256) void scatter_kernel(const int* __restrict__ ei32) {
    int e = blockIdx.x * blockDim.x + threadIdx.x;
    if (e >= N_EDGES) return;
    int src, dst;
    if (g_is64) {
        const long long* ei = (const long long*)ei32;
        src = (int)ei[e];
        dst = (int)ei[N_EDGES + e];
    } else {
        src = ei32[e];
        dst = ei32[N_EDGES + e];
    }
    int pos = atomicAdd(&g_cur[dst], 1);
    g_srcs[pos] = src;
}

// ---------------- GEMM h = x @ W^T with 4x4 register tiles ----------------
// Block: 256 threads = 8 warps. Block computes 32 rows x 128 cols.
// Warp ty owns rows [ty*4, ty*4+4); lane tx owns cols {tx, tx+32, tx+64, tx+96}
// (one column per head -> alpha reduction is a full-warp shfl sum per head).
// W staged in 32-k chunks to stay under the 48KB static smem limit
// (xs 16.9KB + Ws 16.5KB = 33.4KB -> 2 CTAs/SM).
#define BM 32
#define KC 32
__global__ __launch_bounds__(256) void gemm_alpha_kernel(
    const float* __restrict__ x,
    const float* __restrict__ W,
    const float* __restrict__ a)
{
    __shared__ float xs[IN_F][BM + 1];   // x transposed: xs[k][m]
    __shared__ float Ws[KC][129];        // W transposed chunk: Ws[kk][c]

    const int t  = threadIdx.x;
    const int tx = t & 31;
    const int ty = t >> 5;
    const int rowbase = blockIdx.x * BM;

    // stage x tile transposed (coalesced gmem read, conflict-free smem write)
    for (int i = t; i < BM * IN_F; i += 256) {
        int m = i >> 7, k = i & 127;
        int row = rowbase + m;
        xs[k][m] = (row < N_NODES) ? x[row * IN_F + k] : 0.f;
    }

    float acc[4][4];
    #pragma unroll
    for (int i = 0; i < 4; i++)
        #pragma unroll
        for (int j = 0; j < 4; j++) acc[i][j] = 0.f;

    for (int chunk = 0; chunk < IN_F / KC; chunk++) {
        const int kbase = chunk * KC;
        __syncthreads();
        // stage W chunk transposed: 128 cols x KC slices, 16 elems/thread
        for (int i = t; i < 128 * KC; i += 256) {
            int c = i / KC, kk = i % KC;
            Ws[kk][c] = W[c * IN_F + kbase + kk];
        }
        __syncthreads();

        #pragma unroll 8
        for (int kk = 0; kk < KC; kk++) {
            float xv0 = xs[kbase + kk][ty * 4 + 0];
            float xv1 = xs[kbase + kk][ty * 4 + 1];
            float xv2 = xs[kbase + kk][ty * 4 + 2];
            float xv3 = xs[kbase + kk][ty * 4 + 3];
            float wv0 = Ws[kk][tx];
            float wv1 = Ws[kk][tx + 32];
            float wv2 = Ws[kk][tx + 64];
            float wv3 = Ws[kk][tx + 96];
            acc[0][0] = fmaf(xv0, wv0, acc[0][0]);
            acc[0][1] = fmaf(xv0, wv1, acc[0][1]);
            acc[0][2] = fmaf(xv0, wv2, acc[0][2]);
            acc[0][3] = fmaf(xv0, wv3, acc[0][3]);
            acc[1][0] = fmaf(xv1, wv0, acc[1][0]);
            acc[1][1] = fmaf(xv1, wv1, acc[1][1]);
            acc[1][2] = fmaf(xv1, wv2, acc[1][2]);
            acc[1][3] = fmaf(xv1, wv3, acc[1][3]);
            acc[2][0] = fmaf(xv2, wv0, acc[2][0]);
            acc[2][1] = fmaf(xv2, wv1, acc[2][1]);
            acc[2][2] = fmaf(xv2, wv2, acc[2][2]);
            acc[2][3] = fmaf(xv2, wv3, acc[2][3]);
            acc[3][0] = fmaf(xv3, wv0, acc[3][0]);
            acc[3][1] = fmaf(xv3, wv1, acc[3][1]);
            acc[3][2] = fmaf(xv3, wv2, acc[3][2]);
            acc[3][3] = fmaf(xv3, wv3, acc[3][3]);
        }
    }

    // epilogue: store h, fused alpha_src/alpha_dst reductions
    float as_w[4], ad_w[4];
    #pragma unroll
    for (int j = 0; j < 4; j++) {
        as_w[j] = a[j * 2 * HEAD_DIM + tx];
        ad_w[j] = a[j * 2 * HEAD_DIM + HEAD_DIM + tx];
    }
    const unsigned mask = 0xffffffffu;

    #pragma unroll
    for (int i = 0; i < 4; i++) {
        const int row = rowbase + ty * 4 + i;
        if (row >= N_NODES) break;
        #pragma unroll
        for (int j = 0; j < 4; j++)
            g_h[row * OUT_F + tx + 32 * j] = acc[i][j];
        #pragma unroll
        for (int j = 0; j < 4; j++) {
            float s = acc[i][j] * as_w[j];
            float d = acc[i][j] * ad_w[j];
            #pragma unroll
            for (int off = 16; off > 0; off >>= 1) {
                s += __shfl_xor_sync(mask, s, off);
                d += __shfl_xor_sync(mask, d, off);
            }
            if (tx == 0) {
                g_as[row * HEADS + j] = s;
                g_ad[row * HEADS + j] = d;
            }
        }
    }
}

// ---------------- gather: one warp per dst node, no atomics ---------------
__global__ __launch_bounds__(256) void gather_kernel(float* __restrict__ out) {
    const int n    = blockIdx.x * 8 + (threadIdx.x >> 5);
    const int lane = threadIdx.x & 31;
    if (n >= N_NODES) return;

    const int start = g_off[n];
    const int end   = g_off[n + 1];
    const float myad = (lane < HEADS) ? g_ad[n * HEADS + lane] : 0.f;
    const unsigned mask = 0xffffffffu;

    float4 acc = make_float4(0.f, 0.f, 0.f, 0.f);

    int e = start;
    #pragma unroll 1
    while (e + 2 <= end) {
        const int s0 = g_srcs[e];
        const int s1 = g_srcs[e + 1];
        float v0 = 0.f, v1 = 0.f;
        if (lane < HEADS) {
            float t0 = g_as[s0 * HEADS + lane] + myad;
            float t1 = g_as[s1 * HEADS + lane] + myad;
            v0 = (t0 > 0.f) ? t0 : NEG_SLOPE * t0;
            v1 = (t1 > 0.f) ? t1 : NEG_SLOPE * t1;
        }
        const float a0 = __shfl_sync(mask, v0, lane >> 3);
        const float a1 = __shfl_sync(mask, v1, lane >> 3);
        const float4 h0 = *(const float4*)&g_h[s0 * OUT_F + lane * 4];
        const float4 h1 = *(const float4*)&g_h[s1 * OUT_F + lane * 4];
        acc.x = fmaf(a0, h0.x, acc.x); acc.y = fmaf(a0, h0.y, acc.y);
        acc.z = fmaf(a0, h0.z, acc.z); acc.w = fmaf(a0, h0.w, acc.w);
        acc.x = fmaf(a1, h1.x, acc.x); acc.y = fmaf(a1, h1.y, acc.y);
        acc.z = fmaf(a1, h1.z, acc.z); acc.w = fmaf(a1, h1.w, acc.w);
        e += 2;
    }
    if (e < end) {
        const int s0 = g_srcs[e];
        float v0 = 0.f;
        if (lane < HEADS) {
            float t0 = g_as[s0 * HEADS + lane] + myad;
            v0 = (t0 > 0.f) ? t0 : NEG_SLOPE * t0;
        }
        const float a0 = __shfl_sync(mask, v0, lane >> 3);
        const float4 h0 = *(const float4*)&g_h[s0 * OUT_F + lane * 4];
        acc.x = fmaf(a0, h0.x, acc.x); acc.y = fmaf(a0, h0.y, acc.y);
        acc.z = fmaf(a0, h0.z, acc.z); acc.w = fmaf(a0, h0.w, acc.w);
    }

    *(float4*)&out[(size_t)n * OUT_F + lane * 4] = acc;
}

// ---------------- launch -------------------------------------------------
extern "C" void kernel_launch(void* const* d_in, const int* in_sizes, int n_in,
                              void* d_out, int out_size) {
    const float* x  = (const float*)d_in[0];
    const int*   ei = (const int*)d_in[1];   // int32 or int64 (detected on device)
    const float* W  = (const float*)d_in[2];
    const float* a  = (const float*)d_in[3];
    float* out = (float*)d_out;

    detect_kernel<<<1, 32>>>(ei);
    zero_cnt_kernel<<<(N_NODES + 255) / 256, 256>>>();

    gemm_alpha_kernel<<<(N_NODES + BM - 1) / BM, 256>>>(x, W, a);

    const int eblocks = (N_EDGES + 255) / 256;
    hist_kernel<<<eblocks, 256>>>(ei);
    scan_kernel<<<1, 1024>>>();
    scatter_kernel<<<eblocks, 256>>>(ei);

    gather_kernel<<<(N_NODES + 7) / 8, 256>>>(out);
}

// round 4
// speedup vs baseline: 1.4031x; 1.2084x over previous
#include <cuda_runtime.h>
#include <cuda_fp16.h>
#include <stdint.h>

#define N_NODES  50000
#define N_EDGES  1600000
#define IN_F     128
#define OUT_F    128
#define HEADS    4
#define HEAD_DIM 32
#define NEG_SLOPE 0.2f

#define GEMM_BM     32
#define GEMM_BLOCKS 1563            // ceil(50000/32)
#define SCAT_BLOCKS 3125            // 1.6M edges / (256 thr * 2 edges)

// ---------------- device scratch ----------------
__device__ __half2 g_h2[N_NODES * (OUT_F / 2)];  // h as half2 (12.8 MB)
__device__ float   g_as[N_NODES * HEADS];
__device__ float   g_ad[N_NODES * HEADS];
__device__ float   g_Wt[IN_F * OUT_F];           // W transposed: g_Wt[k*128+c]
__device__ int     g_cnt[N_NODES];
__device__ int     g_off[N_NODES + 1];
__device__ int     g_cur[N_NODES];
__device__ int     g_srcs[N_EDGES];
__device__ int     g_is64;

// ---------------- init: zero hist + dtype detect + W transpose -----------
#define ZERO_BLOCKS 196
__global__ __launch_bounds__(256) void init_kernel(
    const int* __restrict__ ei, const float* __restrict__ W)
{
    const int b = blockIdx.x;
    const int t = threadIdx.x;
    if (b < ZERO_BLOCKS) {
        int i = b * 256 + t;
        if (i < N_NODES) g_cnt[i] = 0;
        if (b == 0 && t == 0) {
            int allzero = 1;
            #pragma unroll 1
            for (int i2 = 1; i2 < 256; i2 += 2)
                if (ei[i2] != 0) { allzero = 0; break; }
            g_is64 = allzero;
        }
    } else {
        // transpose W (coalesced read, scattered write; 64KB total)
        int lin = (b - ZERO_BLOCKS) * 256 + t;   // 64 blocks * 256 = 16384
        int c = lin >> 7, k = lin & 127;
        g_Wt[k * OUT_F + c] = W[c * IN_F + k];
    }
}

// ---------------- histogram of dst (4 edges/thread) -----------------------
__global__ __launch_bounds__(256) void hist_kernel(const int* __restrict__ ei32) {
    const int e4 = (blockIdx.x * blockDim.x + threadIdx.x) * 4;
    if (e4 >= N_EDGES) return;
    int d0, d1, d2, d3;
    if (g_is64) {
        const longlong2* p = (const longlong2*)((const long long*)ei32 + N_EDGES + e4);
        longlong2 a = p[0], b = p[1];
        d0 = (int)a.x; d1 = (int)a.y; d2 = (int)b.x; d3 = (int)b.y;
    } else {
        int4 d = *(const int4*)(ei32 + N_EDGES + e4);
        d0 = d.x; d1 = d.y; d2 = d.z; d3 = d.w;
    }
    atomicAdd(&g_cnt[d0], 1);
    atomicAdd(&g_cnt[d1], 1);
    atomicAdd(&g_cnt[d2], 1);
    atomicAdd(&g_cnt[d3], 1);
}

// ---------------- single-CTA warp-shuffle scan ----------------------------
__global__ __launch_bounds__(1024) void scan_kernel() {
    __shared__ int warp_tot[32];
    const int t = threadIdx.x;
    const int lane = t & 31, wid = t >> 5;
    const int CH = (N_NODES + 1023) / 1024;      // 49
    const int base = t * CH;
    const unsigned m = 0xffffffffu;

    int sum = 0;
    #pragma unroll 1
    for (int i = 0; i < CH; i++) {
        int idx = base + i;
        if (idx < N_NODES) sum += g_cnt[idx];
    }
    // inclusive warp scan
    int v = sum;
    #pragma unroll
    for (int off = 1; off < 32; off <<= 1) {
        int u = __shfl_up_sync(m, v, off);
        if (lane >= off) v += u;
    }
    if (lane == 31) warp_tot[wid] = v;
    __syncthreads();
    if (wid == 0) {
        int w = warp_tot[lane];
        #pragma unroll
        for (int off = 1; off < 32; off <<= 1) {
            int u = __shfl_up_sync(m, w, off);
            if (lane >= off) w += u;
        }
        warp_tot[lane] = w;
    }
    __syncthreads();
    int run = (v - sum) + (wid > 0 ? warp_tot[wid - 1] : 0);  // exclusive prefix
    #pragma unroll 1
    for (int i = 0; i < CH; i++) {
        int idx = base + i;
        if (idx < N_NODES) {
            g_off[idx] = run;
            g_cur[idx] = run;
            run += g_cnt[idx];
        }
    }
    if (t == 1023) g_off[N_NODES] = run;
}

// ---------------- fused GEMM (h = x@W^T + alpha) || scatter ----------------
// GEMM blocks: 256 thr, 32 rows x 128 cols. Warp ty owns rows ty*4..+3;
// lane tx owns cols 4tx..4tx+3 (all in head tx>>3 -> 8-lane alpha reduce).
// W read from g_Wt via L1 (resident, 64KB). x tile in smem, float4 broadcast.
__global__ __launch_bounds__(256) void gemm_scatter_kernel(
    const float* __restrict__ x,
    const int*   __restrict__ ei32,
    const float* __restrict__ a)
{
    __shared__ float xs[GEMM_BM][IN_F + 4];

    if (blockIdx.x >= GEMM_BLOCKS) {
        // ---- scatter path: 2 edges per thread ----
        const int e = (blockIdx.x - GEMM_BLOCKS) * 512 + threadIdx.x * 2;
        int s0, s1, d0, d1;
        if (g_is64) {
            const long long* ei = (const long long*)ei32;
            longlong2 sv = *(const longlong2*)(ei + e);
            longlong2 dv = *(const longlong2*)(ei + N_EDGES + e);
            s0 = (int)sv.x; s1 = (int)sv.y; d0 = (int)dv.x; d1 = (int)dv.y;
        } else {
            int2 sv = *(const int2*)(ei32 + e);
            int2 dv = *(const int2*)(ei32 + N_EDGES + e);
            s0 = sv.x; s1 = sv.y; d0 = dv.x; d1 = dv.y;
        }
        int p0 = atomicAdd(&g_cur[d0], 1);
        g_srcs[p0] = s0;
        int p1 = atomicAdd(&g_cur[d1], 1);
        g_srcs[p1] = s1;
        return;
    }

    // ---- GEMM path ----
    const int t  = threadIdx.x;
    const int tx = t & 31;
    const int ty = t >> 5;
    const int rowbase = blockIdx.x * GEMM_BM;

    // stage x tile (float4 coalesced, conflict-free)
    for (int f = t; f < GEMM_BM * 32; f += 256) {
        int mm = f >> 5, k4 = f & 31;
        int row = rowbase + mm;
        float4 v = make_float4(0.f, 0.f, 0.f, 0.f);
        if (row < N_NODES) v = *(const float4*)(x + (size_t)row * IN_F + k4 * 4);
        *(float4*)&xs[mm][k4 * 4] = v;
    }
    __syncthreads();

    float acc[4][4];
    #pragma unroll
    for (int i = 0; i < 4; i++)
        #pragma unroll
        for (int j = 0; j < 4; j++) acc[i][j] = 0.f;

    const float4* wt4 = (const float4*)g_Wt;
    const int m0 = ty * 4;

    #pragma unroll 2
    for (int k = 0; k < IN_F; k += 4) {
        float4 xr[4], wr[4];
        #pragma unroll
        for (int i = 0; i < 4; i++)
            xr[i] = *(const float4*)&xs[m0 + i][k];      // broadcast
        #pragma unroll
        for (int q = 0; q < 4; q++)
            wr[q] = wt4[(k + q) * 32 + tx];              // L1 hit
        #pragma unroll
        for (int i = 0; i < 4; i++) {
            acc[i][0] = fmaf(xr[i].x, wr[0].x, acc[i][0]);
            acc[i][1] = fmaf(xr[i].x, wr[0].y, acc[i][1]);
            acc[i][2] = fmaf(xr[i].x, wr[0].z, acc[i][2]);
            acc[i][3] = fmaf(xr[i].x, wr[0].w, acc[i][3]);
            acc[i][0] = fmaf(xr[i].y, wr[1].x, acc[i][0]);
            acc[i][1] = fmaf(xr[i].y, wr[1].y, acc[i][1]);
            acc[i][2] = fmaf(xr[i].y, wr[1].z, acc[i][2]);
            acc[i][3] = fmaf(xr[i].y, wr[1].w, acc[i][3]);
            acc[i][0] = fmaf(xr[i].z, wr[2].x, acc[i][0]);
            acc[i][1] = fmaf(xr[i].z, wr[2].y, acc[i][1]);
            acc[i][2] = fmaf(xr[i].z, wr[2].z, acc[i][2]);
            acc[i][3] = fmaf(xr[i].z, wr[2].w, acc[i][3]);
            acc[i][0] = fmaf(xr[i].w, wr[3].x, acc[i][0]);
            acc[i][1] = fmaf(xr[i].w, wr[3].y, acc[i][1]);
            acc[i][2] = fmaf(xr[i].w, wr[3].z, acc[i][2]);
            acc[i][3] = fmaf(xr[i].w, wr[3].w, acc[i][3]);
        }
    }

    // epilogue: h -> half2, fused alpha reductions (8-lane segmented)
    const int head = tx >> 3;
    const int d0c  = (tx & 7) * 4;
    float as_v[4], ad_v[4];
    #pragma unroll
    for (int j = 0; j < 4; j++) {
        as_v[j] = a[head * 2 * HEAD_DIM + d0c + j];
        ad_v[j] = a[head * 2 * HEAD_DIM + HEAD_DIM + d0c + j];
    }
    const unsigned msk = 0xffffffffu;

    #pragma unroll
    for (int i = 0; i < 4; i++) {
        const int row = rowbase + m0 + i;
        if (row >= N_NODES) break;
        __half2 p0 = __floats2half2_rn(acc[i][0], acc[i][1]);
        __half2 p1 = __floats2half2_rn(acc[i][2], acc[i][3]);
        uint2 u;
        u.x = *(const unsigned*)&p0;
        u.y = *(const unsigned*)&p1;
        *(uint2*)&g_h2[(size_t)row * 64 + tx * 2] = u;

        float s = acc[i][0] * as_v[0] + acc[i][1] * as_v[1]
                + acc[i][2] * as_v[2] + acc[i][3] * as_v[3];
        float d = acc[i][0] * ad_v[0] + acc[i][1] * ad_v[1]
                + acc[i][2] * ad_v[2] + acc[i][3] * ad_v[3];
        #pragma unroll
        for (int off = 1; off < 8; off <<= 1) {
            s += __shfl_xor_sync(msk, s, off);
            d += __shfl_xor_sync(msk, d, off);
        }
        if ((tx & 7) == 0) {
            g_as[row * HEADS + head] = s;
            g_ad[row * HEADS + head] = d;
        }
    }
}

// ---------------- gather: one warp per dst node, unroll 4 -----------------
__device__ __forceinline__ float leaky(float v) {
    return (v > 0.f) ? v : NEG_SLOPE * v;
}

__global__ __launch_bounds__(256) void gather_kernel(float* __restrict__ out) {
    const int n    = blockIdx.x * 8 + (threadIdx.x >> 5);
    const int lane = threadIdx.x & 31;
    if (n >= N_NODES) return;

    const int start = g_off[n];
    const int end   = g_off[n + 1];
    const float myad = (lane < HEADS) ? g_ad[n * HEADS + lane] : 0.f;
    const unsigned msk = 0xffffffffu;
    const int hsel = lane >> 3;

    float4 acc = make_float4(0.f, 0.f, 0.f, 0.f);

    int e = start;
    #pragma unroll 1
    for (; e + 4 <= end; e += 4) {
        int s0 = g_srcs[e], s1 = g_srcs[e + 1], s2 = g_srcs[e + 2], s3 = g_srcs[e + 3];
        float v0 = 0.f, v1 = 0.f, v2 = 0.f, v3 = 0.f;
        if (lane < HEADS) {
            v0 = leaky(g_as[s0 * HEADS + lane] + myad);
            v1 = leaky(g_as[s1 * HEADS + lane] + myad);
            v2 = leaky(g_as[s2 * HEADS + lane] + myad);
            v3 = leaky(g_as[s3 * HEADS + lane] + myad);
        }
        float a0 = __shfl_sync(msk, v0, hsel);
        float a1 = __shfl_sync(msk, v1, hsel);
        float a2 = __shfl_sync(msk, v2, hsel);
        float a3 = __shfl_sync(msk, v3, hsel);
        uint2 u0 = *(const uint2*)&g_h2[(size_t)s0 * 64 + lane * 2];
        uint2 u1 = *(const uint2*)&g_h2[(size_t)s1 * 64 + lane * 2];
        uint2 u2 = *(const uint2*)&g_h2[(size_t)s2 * 64 + lane * 2];
        uint2 u3 = *(const uint2*)&g_h2[(size_t)s3 * 64 + lane * 2];
        float2 f;
        f = __half22float2(*(__half2*)&u0.x); acc.x = fmaf(a0, f.x, acc.x); acc.y = fmaf(a0, f.y, acc.y);
        f = __half22float2(*(__half2*)&u0.y); acc.z = fmaf(a0, f.x, acc.z); acc.w = fmaf(a0, f.y, acc.w);
        f = __half22float2(*(__half2*)&u1.x); acc.x = fmaf(a1, f.x, acc.x); acc.y = fmaf(a1, f.y, acc.y);
        f = __half22float2(*(__half2*)&u1.y); acc.z = fmaf(a1, f.x, acc.z); acc.w = fmaf(a1, f.y, acc.w);
        f = __half22float2(*(__half2*)&u2.x); acc.x = fmaf(a2, f.x, acc.x); acc.y = fmaf(a2, f.y, acc.y);
        f = __half22float2(*(__half2*)&u2.y); acc.z = fmaf(a2, f.x, acc.z); acc.w = fmaf(a2, f.y, acc.w);
        f = __half22float2(*(__half2*)&u3.x); acc.x = fmaf(a3, f.x, acc.x); acc.y = fmaf(a3, f.y, acc.y);
        f = __half22float2(*(__half2*)&u3.y); acc.z = fmaf(a3, f.x, acc.z); acc.w = fmaf(a3, f.y, acc.w);
    }
    #pragma unroll 1
    for (; e < end; e++) {
        int s0 = g_srcs[e];
        float v0 = 0.f;
        if (lane < HEADS) v0 = leaky(g_as[s0 * HEADS + lane] + myad);
        float a0 = __shfl_sync(msk, v0, hsel);
        uint2 u0 = *(const uint2*)&g_h2[(size_t)s0 * 64 + lane * 2];
        float2 f;
        f = __half22float2(*(__half2*)&u0.x); acc.x = fmaf(a0, f.x, acc.x); acc.y = fmaf(a0, f.y, acc.y);
        f = __half22float2(*(__half2*)&u0.y); acc.z = fmaf(a0, f.x, acc.z); acc.w = fmaf(a0, f.y, acc.w);
    }

    *(float4*)&out[(size_t)n * OUT_F + lane * 4] = acc;
}

// ---------------- launch -------------------------------------------------
extern "C" void kernel_launch(void* const* d_in, const int* in_sizes, int n_in,
                              void* d_out, int out_size) {
    const float* x  = (const float*)d_in[0];
    const int*   ei = (const int*)d_in[1];
    const float* W  = (const float*)d_in[2];
    const float* a  = (const float*)d_in[3];
    float* out = (float*)d_out;

    init_kernel<<<ZERO_BLOCKS + 64, 256>>>(ei, W);
    hist_kernel<<<(N_EDGES / 4 + 255) / 256, 256>>>(ei);
    scan_kernel<<<1, 1024>>>();
    gemm_scatter_kernel<<<GEMM_BLOCKS + SCAT_BLOCKS, 256>>>(x, ei, a);
    gather_kernel<<<(N_NODES + 7) / 8, 256>>>(out);
}

// round 5
// speedup vs baseline: 1.4104x; 1.0052x over previous
#include <cuda_runtime.h>
#include <cuda_fp16.h>
#include <stdint.h>

#define N_NODES  50000
#define N_EDGES  1600000
#define IN_F     128
#define OUT_F    128
#define HEADS    4
#define HEAD_DIM 32
#define NEG_SLOPE 0.2f

#define GEMM_BM     32
#define GEMM_BLOCKS 1563            // ceil(50000/32)
#define SCAT_BLOCKS 3125            // 1.6M edges / (256 thr * 2 edges)

// ---------------- device scratch ----------------
__device__ __half2 g_h2[N_NODES * (OUT_F / 2)];  // h as half2 (12.8 MB)
__device__ float   g_as[N_NODES * HEADS];
__device__ float   g_ad[N_NODES * HEADS];
__device__ float   g_Wt[IN_F * OUT_F];           // W transposed: g_Wt[k*128+c]
__device__ int     g_cnt[N_NODES];
__device__ int     g_off[N_NODES + 1];
__device__ int     g_cur[N_NODES];
__device__ int     g_srcs[N_EDGES];
__device__ int     g_is64;

// ---------------- init: zero hist + dtype detect + W transpose -----------
#define ZERO_BLOCKS 196
__global__ __launch_bounds__(256) void init_kernel(
    const int* __restrict__ ei, const float* __restrict__ W)
{
    const int b = blockIdx.x;
    const int t = threadIdx.x;
    if (b < ZERO_BLOCKS) {
        int i = b * 256 + t;
        if (i < N_NODES) g_cnt[i] = 0;
        if (b == 0 && t == 0) {
            int allzero = 1;
            #pragma unroll 1
            for (int i2 = 1; i2 < 256; i2 += 2)
                if (ei[i2] != 0) { allzero = 0; break; }
            g_is64 = allzero;
        }
    } else {
        // transpose W (coalesced read, scattered write; 64KB total)
        int lin = (b - ZERO_BLOCKS) * 256 + t;   // 64 blocks * 256 = 16384
        int c = lin >> 7, k = lin & 127;
        g_Wt[k * OUT_F + c] = W[c * IN_F + k];
    }
}

// ---------------- histogram of dst (4 edges/thread) -----------------------
__global__ __launch_bounds__(256) void hist_kernel(const int* __restrict__ ei32) {
    const int e4 = (blockIdx.x * blockDim.x + threadIdx.x) * 4;
    if (e4 >= N_EDGES) return;
    int d0, d1, d2, d3;
    if (g_is64) {
        const longlong2* p = (const longlong2*)((const long long*)ei32 + N_EDGES + e4);
        longlong2 a = p[0], b = p[1];
        d0 = (int)a.x; d1 = (int)a.y; d2 = (int)b.x; d3 = (int)b.y;
    } else {
        int4 d = *(const int4*)(ei32 + N_EDGES + e4);
        d0 = d.x; d1 = d.y; d2 = d.z; d3 = d.w;
    }
    atomicAdd(&g_cnt[d0], 1);
    atomicAdd(&g_cnt[d1], 1);
    atomicAdd(&g_cnt[d2], 1);
    atomicAdd(&g_cnt[d3], 1);
}

// ---------------- single-CTA warp-shuffle scan ----------------------------
__global__ __launch_bounds__(1024) void scan_kernel() {
    __shared__ int warp_tot[32];
    const int t = threadIdx.x;
    const int lane = t & 31, wid = t >> 5;
    const int CH = (N_NODES + 1023) / 1024;      // 49
    const int base = t * CH;
    const unsigned m = 0xffffffffu;

    int sum = 0;
    #pragma unroll 1
    for (int i = 0; i < CH; i++) {
        int idx = base + i;
        if (idx < N_NODES) sum += g_cnt[idx];
    }
    // inclusive warp scan
    int v = sum;
    #pragma unroll
    for (int off = 1; off < 32; off <<= 1) {
        int u = __shfl_up_sync(m, v, off);
        if (lane >= off) v += u;
    }
    if (lane == 31) warp_tot[wid] = v;
    __syncthreads();
    if (wid == 0) {
        int w = warp_tot[lane];
        #pragma unroll
        for (int off = 1; off < 32; off <<= 1) {
            int u = __shfl_up_sync(m, w, off);
            if (lane >= off) w += u;
        }
        warp_tot[lane] = w;
    }
    __syncthreads();
    int run = (v - sum) + (wid > 0 ? warp_tot[wid - 1] : 0);  // exclusive prefix
    #pragma unroll 1
    for (int i = 0; i < CH; i++) {
        int idx = base + i;
        if (idx < N_NODES) {
            g_off[idx] = run;
            g_cur[idx] = run;
            run += g_cnt[idx];
        }
    }
    if (t == 1023) g_off[N_NODES] = run;
}

// ---------------- fused GEMM (h = x@W^T + alpha) || scatter ----------------
// GEMM blocks: 256 thr, 32 rows x 128 cols. Warp ty owns rows ty*4..+3;
// lane tx owns cols 4tx..4tx+3 (all in head tx>>3 -> 8-lane alpha reduce).
// W read from g_Wt via L1 (resident, 64KB). x tile in smem, float4 broadcast.
__global__ __launch_bounds__(256) void gemm_scatter_kernel(
    const float* __restrict__ x,
    const int*   __restrict__ ei32,
    const float* __restrict__ a)
{
    __shared__ float xs[GEMM_BM][IN_F + 4];

    if (blockIdx.x >= GEMM_BLOCKS) {
        // ---- scatter path: 2 edges per thread ----
        const int e = (blockIdx.x - GEMM_BLOCKS) * 512 + threadIdx.x * 2;
        int s0, s1, d0, d1;
        if (g_is64) {
            const long long* ei = (const long long*)ei32;
            longlong2 sv = *(const longlong2*)(ei + e);
            longlong2 dv = *(const longlong2*)(ei + N_EDGES + e);
            s0 = (int)sv.x; s1 = (int)sv.y; d0 = (int)dv.x; d1 = (int)dv.y;
        } else {
            int2 sv = *(const int2*)(ei32 + e);
            int2 dv = *(const int2*)(ei32 + N_EDGES + e);
            s0 = sv.x; s1 = sv.y; d0 = dv.x; d1 = dv.y;
        }
        int p0 = atomicAdd(&g_cur[d0], 1);
        g_srcs[p0] = s0;
        int p1 = atomicAdd(&g_cur[d1], 1);
        g_srcs[p1] = s1;
        return;
    }

    // ---- GEMM path ----
    const int t  = threadIdx.x;
    const int tx = t & 31;
    const int ty = t >> 5;
    const int rowbase = blockIdx.x * GEMM_BM;

    // stage x tile (float4 coalesced, conflict-free)
    for (int f = t; f < GEMM_BM * 32; f += 256) {
        int mm = f >> 5, k4 = f & 31;
        int row = rowbase + mm;
        float4 v = make_float4(0.f, 0.f, 0.f, 0.f);
        if (row < N_NODES) v = *(const float4*)(x + (size_t)row * IN_F + k4 * 4);
        *(float4*)&xs[mm][k4 * 4] = v;
    }
    __syncthreads();

    float acc[4][4];
    #pragma unroll
    for (int i = 0; i < 4; i++)
        #pragma unroll
        for (int j = 0; j < 4; j++) acc[i][j] = 0.f;

    const float4* wt4 = (const float4*)g_Wt;
    const int m0 = ty * 4;

    #pragma unroll 2
    for (int k = 0; k < IN_F; k += 4) {
        float4 xr[4], wr[4];
        #pragma unroll
        for (int i = 0; i < 4; i++)
            xr[i] = *(const float4*)&xs[m0 + i][k];      // broadcast
        #pragma unroll
        for (int q = 0; q < 4; q++)
            wr[q] = wt4[(k + q) * 32 + tx];              // L1 hit
        #pragma unroll
        for (int i = 0; i < 4; i++) {
            acc[i][0] = fmaf(xr[i].x, wr[0].x, acc[i][0]);
            acc[i][1] = fmaf(xr[i].x, wr[0].y, acc[i][1]);
            acc[i][2] = fmaf(xr[i].x, wr[0].z, acc[i][2]);
            acc[i][3] = fmaf(xr[i].x, wr[0].w, acc[i][3]);
            acc[i][0] = fmaf(xr[i].y, wr[1].x, acc[i][0]);
            acc[i][1] = fmaf(xr[i].y, wr[1].y, acc[i][1]);
            acc[i][2] = fmaf(xr[i].y, wr[1].z, acc[i][2]);
            acc[i][3] = fmaf(xr[i].y, wr[1].w, acc[i][3]);
            acc[i][0] = fmaf(xr[i].z, wr[2].x, acc[i][0]);
            acc[i][1] = fmaf(xr[i].z, wr[2].y, acc[i][1]);
            acc[i][2] = fmaf(xr[i].z, wr[2].z, acc[i][2]);
            acc[i][3] = fmaf(xr[i].z, wr[2].w, acc[i][3]);
            acc[i][0] = fmaf(xr[i].w, wr[3].x, acc[i][0]);
            acc[i][1] = fmaf(xr[i].w, wr[3].y, acc[i][1]);
            acc[i][2] = fmaf(xr[i].w, wr[3].z, acc[i][2]);
            acc[i][3] = fmaf(xr[i].w, wr[3].w, acc[i][3]);
        }
    }

    // epilogue: h -> half2, fused alpha reductions (8-lane segmented)
    const int head = tx >> 3;
    const int d0c  = (tx & 7) * 4;
    float as_v[4], ad_v[4];
    #pragma unroll
    for (int j = 0; j < 4; j++) {
        as_v[j] = a[head * 2 * HEAD_DIM + d0c + j];
        ad_v[j] = a[head * 2 * HEAD_DIM + HEAD_DIM + d0c + j];
    }
    const unsigned msk = 0xffffffffu;

    #pragma unroll
    for (int i = 0; i < 4; i++) {
        const int row = rowbase + m0 + i;
        if (row >= N_NODES) break;
        __half2 p0 = __floats2half2_rn(acc[i][0], acc[i][1]);
        __half2 p1 = __floats2half2_rn(acc[i][2], acc[i][3]);
        uint2 u;
        u.x = *(const unsigned*)&p0;
        u.y = *(const unsigned*)&p1;
        *(uint2*)&g_h2[(size_t)row * 64 + tx * 2] = u;

        float s = acc[i][0] * as_v[0] + acc[i][1] * as_v[1]
                + acc[i][2] * as_v[2] + acc[i][3] * as_v[3];
        float d = acc[i][0] * ad_v[0] + acc[i][1] * ad_v[1]
                + acc[i][2] * ad_v[2] + acc[i][3] * ad_v[3];
        #pragma unroll
        for (int off = 1; off < 8; off <<= 1) {
            s += __shfl_xor_sync(msk, s, off);
            d += __shfl_xor_sync(msk, d, off);
        }
        if ((tx & 7) == 0) {
            g_as[row * HEADS + head] = s;
            g_ad[row * HEADS + head] = d;
        }
    }
}

// ---------------- gather: one warp per dst node, unroll 4 -----------------
__device__ __forceinline__ float leaky(float v) {
    return (v > 0.f) ? v : NEG_SLOPE * v;
}

__global__ __launch_bounds__(256) void gather_kernel(float* __restrict__ out) {
    const int n    = blockIdx.x * 8 + (threadIdx.x >> 5);
    const int lane = threadIdx.x & 31;
    if (n >= N_NODES) return;

    const int start = g_off[n];
    const int end   = g_off[n + 1];
    const float myad = (lane < HEADS) ? g_ad[n * HEADS + lane] : 0.f;
    const unsigned msk = 0xffffffffu;
    const int hsel = lane >> 3;

    float4 acc = make_float4(0.f, 0.f, 0.f, 0.f);

    int e = start;
    #pragma unroll 1
    for (; e + 4 <= end; e += 4) {
        int s0 = g_srcs[e], s1 = g_srcs[e + 1], s2 = g_srcs[e + 2], s3 = g_srcs[e + 3];
        float v0 = 0.f, v1 = 0.f, v2 = 0.f, v3 = 0.f;
        if (lane < HEADS) {
            v0 = leaky(g_as[s0 * HEADS + lane] + myad);
            v1 = leaky(g_as[s1 * HEADS + lane] + myad);
            v2 = leaky(g_as[s2 * HEADS + lane] + myad);
            v3 = leaky(g_as[s3 * HEADS + lane] + myad);
        }
        float a0 = __shfl_sync(msk, v0, hsel);
        float a1 = __shfl_sync(msk, v1, hsel);
        float a2 = __shfl_sync(msk, v2, hsel);
        float a3 = __shfl_sync(msk, v3, hsel);
        uint2 u0 = *(const uint2*)&g_h2[(size_t)s0 * 64 + lane * 2];
        uint2 u1 = *(const uint2*)&g_h2[(size_t)s1 * 64 + lane * 2];
        uint2 u2 = *(const uint2*)&g_h2[(size_t)s2 * 64 + lane * 2];
        uint2 u3 = *(const uint2*)&g_h2[(size_t)s3 * 64 + lane * 2];
        float2 f;
        f = __half22float2(*(__half2*)&u0.x); acc.x = fmaf(a0, f.x, acc.x); acc.y = fmaf(a0, f.y, acc.y);
        f = __half22float2(*(__half2*)&u0.y); acc.z = fmaf(a0, f.x, acc.z); acc.w = fmaf(a0, f.y, acc.w);
        f = __half22float2(*(__half2*)&u1.x); acc.x = fmaf(a1, f.x, acc.x); acc.y = fmaf(a1, f.y, acc.y);
        f = __half22float2(*(__half2*)&u1.y); acc.z = fmaf(a1, f.x, acc.z); acc.w = fmaf(a1, f.y, acc.w);
        f = __half22float2(*(__half2*)&u2.x); acc.x = fmaf(a2, f.x, acc.x); acc.y = fmaf(a2, f.y, acc.y);
        f = __half22float2(*(__half2*)&u2.y); acc.z = fmaf(a2, f.x, acc.z); acc.w = fmaf(a2, f.y, acc.w);
        f = __half22float2(*(__half2*)&u3.x); acc.x = fmaf(a3, f.x, acc.x); acc.y = fmaf(a3, f.y, acc.y);
        f = __half22float2(*(__half2*)&u3.y); acc.z = fmaf(a3, f.x, acc.z); acc.w = fmaf(a3, f.y, acc.w);
    }
    #pragma unroll 1
    for (; e < end; e++) {
        int s0 = g_srcs[e];
        float v0 = 0.f;
        if (lane < HEADS) v0 = leaky(g_as[s0 * HEADS + lane] + myad);
        float a0 = __shfl_sync(msk, v0, hsel);
        uint2 u0 = *(const uint2*)&g_h2[(size_t)s0 * 64 + lane * 2];
        float2 f;
        f = __half22float2(*(__half2*)&u0.x); acc.x = fmaf(a0, f.x, acc.x); acc.y = fmaf(a0, f.y, acc.y);
        f = __half22float2(*(__half2*)&u0.y); acc.z = fmaf(a0, f.x, acc.z); acc.w = fmaf(a0, f.y, acc.w);
    }

    *(float4*)&out[(size_t)n * OUT_F + lane * 4] = acc;
}

// ---------------- launch -------------------------------------------------
extern "C" void kernel_launch(void* const* d_in, const int* in_sizes, int n_in,
                              void* d_out, int out_size) {
    const float* x  = (const float*)d_in[0];
    const int*   ei = (const int*)d_in[1];
    const float* W  = (const float*)d_in[2];
    const float* a  = (const float*)d_in[3];
    float* out = (float*)d_out;

    init_kernel<<<ZERO_BLOCKS + 64, 256>>>(ei, W);
    hist_kernel<<<(N_EDGES / 4 + 255) / 256, 256>>>(ei);
    scan_kernel<<<1, 1024>>>();
    gemm_scatter_kernel<<<GEMM_BLOCKS + SCAT_BLOCKS, 256>>>(x, ei, a);
    gather_kernel<<<(N_NODES + 7) / 8, 256>>>(out);
}

// round 6
// speedup vs baseline: 1.5648x; 1.1095x over previous
#include <cuda_runtime.h>
#include <cuda_fp16.h>
#include <stdint.h>

#define N_NODES  50000
#define N_EDGES  1600000
#define IN_F     128
#define OUT_F    128
#define HEADS    4
#define HEAD_DIM 32
#define NEG_SLOPE 0.2f

#define GEMM_BM     64
#define GEMM_BLOCKS 782             // ceil(50000/64)
#define SCAT_BLOCKS 3125            // 1.6M edges / (256 thr * 2 edges)

// ---------------- device scratch ----------------
__device__ __half2 g_h2[N_NODES * (OUT_F / 2)];  // h as half2 (12.8 MB)
__device__ float   g_as[N_NODES * HEADS];
__device__ float   g_ad[N_NODES * HEADS];
__device__ float   g_Wt[IN_F * OUT_F];           // W transposed: g_Wt[k*128+c]
__device__ int     g_cnt[N_NODES];
__device__ int     g_off[N_NODES + 1];
__device__ int     g_cur[N_NODES];
__device__ int     g_srcs[N_EDGES];
__device__ int     g_is64;

// ---------------- init: dtype detect + W transpose ------------------------
__global__ __launch_bounds__(256) void init_kernel(
    const int* __restrict__ ei, const float* __restrict__ W)
{
    int lin = blockIdx.x * 256 + threadIdx.x;    // 64 blocks * 256 = 16384
    int c = lin >> 7, k = lin & 127;
    g_Wt[k * OUT_F + c] = W[c * IN_F + k];
    if (lin == 0) {
        int allzero = 1;
        #pragma unroll 1
        for (int i2 = 1; i2 < 256; i2 += 2)
            if (ei[i2] != 0) { allzero = 0; break; }
        g_is64 = allzero;
    }
}

// ---------------- histogram of dst (4 edges/thread) -----------------------
__global__ __launch_bounds__(256) void hist_kernel(const int* __restrict__ ei32) {
    const int e4 = (blockIdx.x * blockDim.x + threadIdx.x) * 4;
    if (e4 >= N_EDGES) return;
    int d0, d1, d2, d3;
    if (g_is64) {
        const longlong2* p = (const longlong2*)((const long long*)ei32 + N_EDGES + e4);
        longlong2 a = p[0], b = p[1];
        d0 = (int)a.x; d1 = (int)a.y; d2 = (int)b.x; d3 = (int)b.y;
    } else {
        int4 d = *(const int4*)(ei32 + N_EDGES + e4);
        d0 = d.x; d1 = d.y; d2 = d.z; d3 = d.w;
    }
    atomicAdd(&g_cnt[d0], 1);
    atomicAdd(&g_cnt[d1], 1);
    atomicAdd(&g_cnt[d2], 1);
    atomicAdd(&g_cnt[d3], 1);
}

// ---------------- single-CTA warp-shuffle scan ----------------------------
__global__ __launch_bounds__(1024) void scan_kernel() {
    __shared__ int warp_tot[32];
    const int t = threadIdx.x;
    const int lane = t & 31, wid = t >> 5;
    const int CH = (N_NODES + 1023) / 1024;      // 49
    const int base = t * CH;
    const unsigned m = 0xffffffffu;

    int sum = 0;
    #pragma unroll 1
    for (int i = 0; i < CH; i++) {
        int idx = base + i;
        if (idx < N_NODES) sum += g_cnt[idx];
    }
    int v = sum;
    #pragma unroll
    for (int off = 1; off < 32; off <<= 1) {
        int u = __shfl_up_sync(m, v, off);
        if (lane >= off) v += u;
    }
    if (lane == 31) warp_tot[wid] = v;
    __syncthreads();
    if (wid == 0) {
        int w = warp_tot[lane];
        #pragma unroll
        for (int off = 1; off < 32; off <<= 1) {
            int u = __shfl_up_sync(m, w, off);
            if (lane >= off) w += u;
        }
        warp_tot[lane] = w;
    }
    __syncthreads();
    int run = (v - sum) + (wid > 0 ? warp_tot[wid - 1] : 0);
    #pragma unroll 1
    for (int i = 0; i < CH; i++) {
        int idx = base + i;
        if (idx < N_NODES) {
            g_off[idx] = run;
            g_cur[idx] = run;
            run += g_cnt[idx];
        }
    }
    if (t == 1023) g_off[N_NODES] = run;
}

// ---------------- fused GEMM (h = x@W^T + alpha) || scatter ----------------
// GEMM blocks: 256 thr, 64 rows x 128 cols. Warp ty owns rows ty*8..+7;
// lane tx owns cols 4tx..4tx+3 (all in head tx>>3 -> 8-lane alpha reduce).
__global__ __launch_bounds__(256) void gemm_scatter_kernel(
    const float* __restrict__ x,
    const int*   __restrict__ ei32,
    const float* __restrict__ a)
{
    __shared__ float xs[GEMM_BM][IN_F + 4];

    if (blockIdx.x >= GEMM_BLOCKS) {
        // ---- scatter path: 2 edges per thread ----
        const int e = (blockIdx.x - GEMM_BLOCKS) * 512 + threadIdx.x * 2;
        int s0, s1, d0, d1;
        if (g_is64) {
            const long long* ei = (const long long*)ei32;
            longlong2 sv = *(const longlong2*)(ei + e);
            longlong2 dv = *(const longlong2*)(ei + N_EDGES + e);
            s0 = (int)sv.x; s1 = (int)sv.y; d0 = (int)dv.x; d1 = (int)dv.y;
        } else {
            int2 sv = *(const int2*)(ei32 + e);
            int2 dv = *(const int2*)(ei32 + N_EDGES + e);
            s0 = sv.x; s1 = sv.y; d0 = dv.x; d1 = dv.y;
        }
        int p0 = atomicAdd(&g_cur[d0], 1);
        g_srcs[p0] = s0;
        int p1 = atomicAdd(&g_cur[d1], 1);
        g_srcs[p1] = s1;
        return;
    }

    // ---- GEMM path ----
    const int t  = threadIdx.x;
    const int tx = t & 31;
    const int ty = t >> 5;
    const int rowbase = blockIdx.x * GEMM_BM;

    for (int f = t; f < GEMM_BM * 32; f += 256) {
        int mm = f >> 5, k4 = f & 31;
        int row = rowbase + mm;
        float4 v = make_float4(0.f, 0.f, 0.f, 0.f);
        if (row < N_NODES) v = *(const float4*)(x + (size_t)row * IN_F + k4 * 4);
        *(float4*)&xs[mm][k4 * 4] = v;
    }
    __syncthreads();

    float acc[8][4];
    #pragma unroll
    for (int i = 0; i < 8; i++)
        #pragma unroll
        for (int j = 0; j < 4; j++) acc[i][j] = 0.f;

    const float4* wt4 = (const float4*)g_Wt;
    const int m0 = ty * 8;

    #pragma unroll 2
    for (int k = 0; k < IN_F; k += 4) {
        float4 wr[4];
        #pragma unroll
        for (int q = 0; q < 4; q++)
            wr[q] = wt4[(k + q) * 32 + tx];
        #pragma unroll
        for (int i = 0; i < 8; i++) {
            float4 xv = *(const float4*)&xs[m0 + i][k];   // broadcast LDS.128
            acc[i][0] = fmaf(xv.x, wr[0].x, acc[i][0]);
            acc[i][1] = fmaf(xv.x, wr[0].y, acc[i][1]);
            acc[i][2] = fmaf(xv.x, wr[0].z, acc[i][2]);
            acc[i][3] = fmaf(xv.x, wr[0].w, acc[i][3]);
            acc[i][0] = fmaf(xv.y, wr[1].x, acc[i][0]);
            acc[i][1] = fmaf(xv.y, wr[1].y, acc[i][1]);
            acc[i][2] = fmaf(xv.y, wr[1].z, acc[i][2]);
            acc[i][3] = fmaf(xv.y, wr[1].w, acc[i][3]);
            acc[i][0] = fmaf(xv.z, wr[2].x, acc[i][0]);
            acc[i][1] = fmaf(xv.z, wr[2].y, acc[i][1]);
            acc[i][2] = fmaf(xv.z, wr[2].z, acc[i][2]);
            acc[i][3] = fmaf(xv.z, wr[2].w, acc[i][3]);
            acc[i][0] = fmaf(xv.w, wr[3].x, acc[i][0]);
            acc[i][1] = fmaf(xv.w, wr[3].y, acc[i][1]);
            acc[i][2] = fmaf(xv.w, wr[3].z, acc[i][2]);
            acc[i][3] = fmaf(xv.w, wr[3].w, acc[i][3]);
        }
    }

    // epilogue: h -> half2, fused alpha reductions (8-lane segmented)
    const int head = tx >> 3;
    const int d0c  = (tx & 7) * 4;
    float as_v[4], ad_v[4];
    #pragma unroll
    for (int j = 0; j < 4; j++) {
        as_v[j] = a[head * 2 * HEAD_DIM + d0c + j];
        ad_v[j] = a[head * 2 * HEAD_DIM + HEAD_DIM + d0c + j];
    }
    const unsigned msk = 0xffffffffu;

    #pragma unroll
    for (int i = 0; i < 8; i++) {
        const int row = rowbase + m0 + i;
        if (row >= N_NODES) break;
        __half2 p0 = __floats2half2_rn(acc[i][0], acc[i][1]);
        __half2 p1 = __floats2half2_rn(acc[i][2], acc[i][3]);
        uint2 u;
        u.x = *(const unsigned*)&p0;
        u.y = *(const unsigned*)&p1;
        *(uint2*)&g_h2[(size_t)row * 64 + tx * 2] = u;

        float s = acc[i][0] * as_v[0] + acc[i][1] * as_v[1]
                + acc[i][2] * as_v[2] + acc[i][3] * as_v[3];
        float d = acc[i][0] * ad_v[0] + acc[i][1] * ad_v[1]
                + acc[i][2] * ad_v[2] + acc[i][3] * ad_v[3];
        #pragma unroll
        for (int off = 1; off < 8; off <<= 1) {
            s += __shfl_xor_sync(msk, s, off);
            d += __shfl_xor_sync(msk, d, off);
        }
        if ((tx & 7) == 0) {
            g_as[row * HEADS + head] = s;
            g_ad[row * HEADS + head] = d;
        }
    }
}

// ---------------- gather: warp per node, half-warp per edge ---------------
// Lanes 0-15 process edge e, lanes 16-31 edge e+1. Each lane owns 8
// contiguous features (one head) -> per-lane independent att, no shuffles
// in the loop. Final combine: shfl_xor(16).
__device__ __forceinline__ float leaky(float v) {
    return (v > 0.f) ? v : NEG_SLOPE * v;
}

__global__ __launch_bounds__(256) void gather_kernel(float* __restrict__ out) {
    const int n = blockIdx.x * 8 + (threadIdx.x >> 5);
    if (n >= N_NODES) return;
    const int lane = threadIdx.x & 31;
    const int hw = lane >> 4;          // which edge of the pair
    const int sl = lane & 15;          // feature-group owner: halfs 8sl..8sl+7
    const int h  = sl >> 2;            // head of those features
    const float myad = g_ad[n * HEADS + h];

    float acc[8];
    #pragma unroll
    for (int j = 0; j < 8; j++) acc[j] = 0.f;

    const int start = g_off[n];
    const int end   = g_off[n + 1];
    int e = start;

    #pragma unroll 1
    for (; e + 4 <= end; e += 4) {
        #pragma unroll
        for (int p = 0; p < 2; p++) {
            const int s = g_srcs[e + 2 * p + hw];
            const float att = leaky(g_as[s * HEADS + h] + myad);
            const uint4 u = *(const uint4*)&g_h2[(size_t)s * 64 + sl * 4];
            float2 f;
            f = __half22float2(*(const __half2*)&u.x);
            acc[0] = fmaf(att, f.x, acc[0]); acc[1] = fmaf(att, f.y, acc[1]);
            f = __half22float2(*(const __half2*)&u.y);
            acc[2] = fmaf(att, f.x, acc[2]); acc[3] = fmaf(att, f.y, acc[3]);
            f = __half22float2(*(const __half2*)&u.z);
            acc[4] = fmaf(att, f.x, acc[4]); acc[5] = fmaf(att, f.y, acc[5]);
            f = __half22float2(*(const __half2*)&u.w);
            acc[6] = fmaf(att, f.x, acc[6]); acc[7] = fmaf(att, f.y, acc[7]);
        }
    }
    #pragma unroll 1
    for (; e < end; e += 2) {
        if (e + hw < end) {
            const int s = g_srcs[e + hw];
            const float att = leaky(g_as[s * HEADS + h] + myad);
            const uint4 u = *(const uint4*)&g_h2[(size_t)s * 64 + sl * 4];
            float2 f;
            f = __half22float2(*(const __half2*)&u.x);
            acc[0] = fmaf(att, f.x, acc[0]); acc[1] = fmaf(att, f.y, acc[1]);
            f = __half22float2(*(const __half2*)&u.y);
            acc[2] = fmaf(att, f.x, acc[2]); acc[3] = fmaf(att, f.y, acc[3]);
            f = __half22float2(*(const __half2*)&u.z);
            acc[4] = fmaf(att, f.x, acc[4]); acc[5] = fmaf(att, f.y, acc[5]);
            f = __half22float2(*(const __half2*)&u.w);
            acc[6] = fmaf(att, f.x, acc[6]); acc[7] = fmaf(att, f.y, acc[7]);
        }
    }

    // combine the two half-warps
    const unsigned msk = 0xffffffffu;
    #pragma unroll
    for (int j = 0; j < 8; j++)
        acc[j] += __shfl_xor_sync(msk, acc[j], 16);

    float* op = out + (size_t)n * OUT_F + sl * 8;
    if (hw == 0)
        *(float4*)op = make_float4(acc[0], acc[1], acc[2], acc[3]);
    else
        *(float4*)(op + 4) = make_float4(acc[4], acc[5], acc[6], acc[7]);
}

// ---------------- launch -------------------------------------------------
extern "C" void kernel_launch(void* const* d_in, const int* in_sizes, int n_in,
                              void* d_out, int out_size) {
    const float* x  = (const float*)d_in[0];
    const int*   ei = (const int*)d_in[1];
    const float* W  = (const float*)d_in[2];
    const float* a  = (const float*)d_in[3];
    float* out = (float*)d_out;

    void* cntp = nullptr;
    cudaGetSymbolAddress(&cntp, g_cnt);
    cudaMemsetAsync(cntp, 0, N_NODES * sizeof(int));

    init_kernel<<<64, 256>>>(ei, W);
    hist_kernel<<<(N_EDGES / 4 + 255) / 256, 256>>>(ei);
    scan_kernel<<<1, 1024>>>();
    gemm_scatter_kernel<<<GEMM_BLOCKS + SCAT_BLOCKS, 256>>>(x, ei, a);
    gather_kernel<<<(N_NODES + 7) / 8, 256>>>(out);
}

// round 7
// speedup vs baseline: 1.5673x; 1.0016x over previous
#include <cuda_runtime.h>
#include <cuda_fp16.h>
#include <stdint.h>

#define N_NODES  50000
#define N_EDGES  1600000
#define IN_F     128
#define OUT_F    128
#define HEADS    4
#define HEAD_DIM 32
#define NEG_SLOPE 0.2f

#define GEMM_BM     64
#define GEMM_BLOCKS 782             // ceil(50000/64)
#define SCAT_BLOCKS 3125            // 1.6M edges / (256 thr * 2 edges)

// ---------------- device scratch ----------------
__device__ __half2 g_h2[N_NODES * (OUT_F / 2)];  // h as half2 (12.8 MB)
__device__ float   g_as[N_NODES * HEADS];
__device__ float   g_ad[N_NODES * HEADS];
__device__ float   g_Wt[IN_F * OUT_F];           // W transposed: g_Wt[k*128+c]
__device__ int     g_cnt[N_NODES];
__device__ int     g_off[N_NODES + 1];
__device__ int     g_cur[N_NODES];
__device__ int     g_srcs[N_EDGES];
__device__ int     g_is64;

// ---------------- init: dtype detect + W transpose ------------------------
__global__ __launch_bounds__(256) void init_kernel(
    const int* __restrict__ ei, const float* __restrict__ W)
{
    int lin = blockIdx.x * 256 + threadIdx.x;    // 64 blocks * 256 = 16384
    int c = lin >> 7, k = lin & 127;
    g_Wt[k * OUT_F + c] = W[c * IN_F + k];
    if (lin == 0) {
        int allzero = 1;
        #pragma unroll 1
        for (int i2 = 1; i2 < 256; i2 += 2)
            if (ei[i2] != 0) { allzero = 0; break; }
        g_is64 = allzero;
    }
}

// ---------------- histogram of dst (4 edges/thread) -----------------------
__global__ __launch_bounds__(256) void hist_kernel(const int* __restrict__ ei32) {
    const int e4 = (blockIdx.x * blockDim.x + threadIdx.x) * 4;
    if (e4 >= N_EDGES) return;
    int d0, d1, d2, d3;
    if (g_is64) {
        const longlong2* p = (const longlong2*)((const long long*)ei32 + N_EDGES + e4);
        longlong2 a = p[0], b = p[1];
        d0 = (int)a.x; d1 = (int)a.y; d2 = (int)b.x; d3 = (int)b.y;
    } else {
        int4 d = *(const int4*)(ei32 + N_EDGES + e4);
        d0 = d.x; d1 = d.y; d2 = d.z; d3 = d.w;
    }
    atomicAdd(&g_cnt[d0], 1);
    atomicAdd(&g_cnt[d1], 1);
    atomicAdd(&g_cnt[d2], 1);
    atomicAdd(&g_cnt[d3], 1);
}

// ---------------- single-CTA warp-shuffle scan ----------------------------
__global__ __launch_bounds__(1024) void scan_kernel() {
    __shared__ int warp_tot[32];
    const int t = threadIdx.x;
    const int lane = t & 31, wid = t >> 5;
    const int CH = (N_NODES + 1023) / 1024;      // 49
    const int base = t * CH;
    const unsigned m = 0xffffffffu;

    int sum = 0;
    #pragma unroll 1
    for (int i = 0; i < CH; i++) {
        int idx = base + i;
        if (idx < N_NODES) sum += g_cnt[idx];
    }
    int v = sum;
    #pragma unroll
    for (int off = 1; off < 32; off <<= 1) {
        int u = __shfl_up_sync(m, v, off);
        if (lane >= off) v += u;
    }
    if (lane == 31) warp_tot[wid] = v;
    __syncthreads();
    if (wid == 0) {
        int w = warp_tot[lane];
        #pragma unroll
        for (int off = 1; off < 32; off <<= 1) {
            int u = __shfl_up_sync(m, w, off);
            if (lane >= off) w += u;
        }
        warp_tot[lane] = w;
    }
    __syncthreads();
    int run = (v - sum) + (wid > 0 ? warp_tot[wid - 1] : 0);
    #pragma unroll 1
    for (int i = 0; i < CH; i++) {
        int idx = base + i;
        if (idx < N_NODES) {
            g_off[idx] = run;
            g_cur[idx] = run;
            run += g_cnt[idx];
        }
    }
    if (t == 1023) g_off[N_NODES] = run;
}

// ---------------- fused GEMM (h = x@W^T + alpha) || scatter ----------------
// GEMM blocks: 256 thr, 64 rows x 128 cols. Warp ty owns rows ty*8..+7;
// lane tx owns cols 4tx..4tx+3 (all in head tx>>3 -> 8-lane alpha reduce).
__global__ __launch_bounds__(256) void gemm_scatter_kernel(
    const float* __restrict__ x,
    const int*   __restrict__ ei32,
    const float* __restrict__ a)
{
    __shared__ float xs[GEMM_BM][IN_F + 4];

    if (blockIdx.x >= GEMM_BLOCKS) {
        // ---- scatter path: 2 edges per thread ----
        const int e = (blockIdx.x - GEMM_BLOCKS) * 512 + threadIdx.x * 2;
        int s0, s1, d0, d1;
        if (g_is64) {
            const long long* ei = (const long long*)ei32;
            longlong2 sv = *(const longlong2*)(ei + e);
            longlong2 dv = *(const longlong2*)(ei + N_EDGES + e);
            s0 = (int)sv.x; s1 = (int)sv.y; d0 = (int)dv.x; d1 = (int)dv.y;
        } else {
            int2 sv = *(const int2*)(ei32 + e);
            int2 dv = *(const int2*)(ei32 + N_EDGES + e);
            s0 = sv.x; s1 = sv.y; d0 = dv.x; d1 = dv.y;
        }
        int p0 = atomicAdd(&g_cur[d0], 1);
        g_srcs[p0] = s0;
        int p1 = atomicAdd(&g_cur[d1], 1);
        g_srcs[p1] = s1;
        return;
    }

    // ---- GEMM path ----
    const int t  = threadIdx.x;
    const int tx = t & 31;
    const int ty = t >> 5;
    const int rowbase = blockIdx.x * GEMM_BM;

    for (int f = t; f < GEMM_BM * 32; f += 256) {
        int mm = f >> 5, k4 = f & 31;
        int row = rowbase + mm;
        float4 v = make_float4(0.f, 0.f, 0.f, 0.f);
        if (row < N_NODES) v = *(const float4*)(x + (size_t)row * IN_F + k4 * 4);
        *(float4*)&xs[mm][k4 * 4] = v;
    }
    __syncthreads();

    float acc[8][4];
    #pragma unroll
    for (int i = 0; i < 8; i++)
        #pragma unroll
        for (int j = 0; j < 4; j++) acc[i][j] = 0.f;

    const float4* wt4 = (const float4*)g_Wt;
    const int m0 = ty * 8;

    #pragma unroll 2
    for (int k = 0; k < IN_F; k += 4) {
        float4 wr[4];
        #pragma unroll
        for (int q = 0; q < 4; q++)
            wr[q] = wt4[(k + q) * 32 + tx];
        #pragma unroll
        for (int i = 0; i < 8; i++) {
            float4 xv = *(const float4*)&xs[m0 + i][k];   // broadcast LDS.128
            acc[i][0] = fmaf(xv.x, wr[0].x, acc[i][0]);
            acc[i][1] = fmaf(xv.x, wr[0].y, acc[i][1]);
            acc[i][2] = fmaf(xv.x, wr[0].z, acc[i][2]);
            acc[i][3] = fmaf(xv.x, wr[0].w, acc[i][3]);
            acc[i][0] = fmaf(xv.y, wr[1].x, acc[i][0]);
            acc[i][1] = fmaf(xv.y, wr[1].y, acc[i][1]);
            acc[i][2] = fmaf(xv.y, wr[1].z, acc[i][2]);
            acc[i][3] = fmaf(xv.y, wr[1].w, acc[i][3]);
            acc[i][0] = fmaf(xv.z, wr[2].x, acc[i][0]);
            acc[i][1] = fmaf(xv.z, wr[2].y, acc[i][1]);
            acc[i][2] = fmaf(xv.z, wr[2].z, acc[i][2]);
            acc[i][3] = fmaf(xv.z, wr[2].w, acc[i][3]);
            acc[i][0] = fmaf(xv.w, wr[3].x, acc[i][0]);
            acc[i][1] = fmaf(xv.w, wr[3].y, acc[i][1]);
            acc[i][2] = fmaf(xv.w, wr[3].z, acc[i][2]);
            acc[i][3] = fmaf(xv.w, wr[3].w, acc[i][3]);
        }
    }

    // epilogue: h -> half2, fused alpha reductions (8-lane segmented)
    const int head = tx >> 3;
    const int d0c  = (tx & 7) * 4;
    float as_v[4], ad_v[4];
    #pragma unroll
    for (int j = 0; j < 4; j++) {
        as_v[j] = a[head * 2 * HEAD_DIM + d0c + j];
        ad_v[j] = a[head * 2 * HEAD_DIM + HEAD_DIM + d0c + j];
    }
    const unsigned msk = 0xffffffffu;

    #pragma unroll
    for (int i = 0; i < 8; i++) {
        const int row = rowbase + m0 + i;
        if (row >= N_NODES) break;
        __half2 p0 = __floats2half2_rn(acc[i][0], acc[i][1]);
        __half2 p1 = __floats2half2_rn(acc[i][2], acc[i][3]);
        uint2 u;
        u.x = *(const unsigned*)&p0;
        u.y = *(const unsigned*)&p1;
        *(uint2*)&g_h2[(size_t)row * 64 + tx * 2] = u;

        float s = acc[i][0] * as_v[0] + acc[i][1] * as_v[1]
                + acc[i][2] * as_v[2] + acc[i][3] * as_v[3];
        float d = acc[i][0] * ad_v[0] + acc[i][1] * ad_v[1]
                + acc[i][2] * ad_v[2] + acc[i][3] * ad_v[3];
        #pragma unroll
        for (int off = 1; off < 8; off <<= 1) {
            s += __shfl_xor_sync(msk, s, off);
            d += __shfl_xor_sync(msk, d, off);
        }
        if ((tx & 7) == 0) {
            g_as[row * HEADS + head] = s;
            g_ad[row * HEADS + head] = d;
        }
    }
}

// ---------------- gather: warp per node, half-warp per edge ---------------
// Lanes 0-15 process edge e, lanes 16-31 edge e+1. Each lane owns 8
// contiguous features (one head) -> per-lane independent att, no shuffles
// in the loop. Final combine: shfl_xor(16).
__device__ __forceinline__ float leaky(float v) {
    return (v > 0.f) ? v : NEG_SLOPE * v;
}

__global__ __launch_bounds__(256) void gather_kernel(float* __restrict__ out) {
    const int n = blockIdx.x * 8 + (threadIdx.x >> 5);
    if (n >= N_NODES) return;
    const int lane = threadIdx.x & 31;
    const int hw = lane >> 4;          // which edge of the pair
    const int sl = lane & 15;          // feature-group owner: halfs 8sl..8sl+7
    const int h  = sl >> 2;            // head of those features
    const float myad = g_ad[n * HEADS + h];

    float acc[8];
    #pragma unroll
    for (int j = 0; j < 8; j++) acc[j] = 0.f;

    const int start = g_off[n];
    const int end   = g_off[n + 1];
    int e = start;

    #pragma unroll 1
    for (; e + 4 <= end; e += 4) {
        #pragma unroll
        for (int p = 0; p < 2; p++) {
            const int s = g_srcs[e + 2 * p + hw];
            const float att = leaky(g_as[s * HEADS + h] + myad);
            const uint4 u = *(const uint4*)&g_h2[(size_t)s * 64 + sl * 4];
            float2 f;
            f = __half22float2(*(const __half2*)&u.x);
            acc[0] = fmaf(att, f.x, acc[0]); acc[1] = fmaf(att, f.y, acc[1]);
            f = __half22float2(*(const __half2*)&u.y);
            acc[2] = fmaf(att, f.x, acc[2]); acc[3] = fmaf(att, f.y, acc[3]);
            f = __half22float2(*(const __half2*)&u.z);
            acc[4] = fmaf(att, f.x, acc[4]); acc[5] = fmaf(att, f.y, acc[5]);
            f = __half22float2(*(const __half2*)&u.w);
            acc[6] = fmaf(att, f.x, acc[6]); acc[7] = fmaf(att, f.y, acc[7]);
        }
    }
    #pragma unroll 1
    for (; e < end; e += 2) {
        if (e + hw < end) {
            const int s = g_srcs[e + hw];
            const float att = leaky(g_as[s * HEADS + h] + myad);
            const uint4 u = *(const uint4*)&g_h2[(size_t)s * 64 + sl * 4];
            float2 f;
            f = __half22float2(*(const __half2*)&u.x);
            acc[0] = fmaf(att, f.x, acc[0]); acc[1] = fmaf(att, f.y, acc[1]);
            f = __half22float2(*(const __half2*)&u.y);
            acc[2] = fmaf(att, f.x, acc[2]); acc[3] = fmaf(att, f.y, acc[3]);
            f = __half22float2(*(const __half2*)&u.z);
            acc[4] = fmaf(att, f.x, acc[4]); acc[5] = fmaf(att, f.y, acc[5]);
            f = __half22float2(*(const __half2*)&u.w);
            acc[6] = fmaf(att, f.x, acc[6]); acc[7] = fmaf(att, f.y, acc[7]);
        }
    }

    // combine the two half-warps
    const unsigned msk = 0xffffffffu;
    #pragma unroll
    for (int j = 0; j < 8; j++)
        acc[j] += __shfl_xor_sync(msk, acc[j], 16);

    float* op = out + (size_t)n * OUT_F + sl * 8;
    if (hw == 0)
        *(float4*)op = make_float4(acc[0], acc[1], acc[2], acc[3]);
    else
        *(float4*)(op + 4) = make_float4(acc[4], acc[5], acc[6], acc[7]);
}

// ---------------- launch -------------------------------------------------
extern "C" void kernel_launch(void* const* d_in, const int* in_sizes, int n_in,
                              void* d_out, int out_size) {
    const float* x  = (const float*)d_in[0];
    const int*   ei = (const int*)d_in[1];
    const float* W  = (const float*)d_in[2];
    const float* a  = (const float*)d_in[3];
    float* out = (float*)d_out;

    void* cntp = nullptr;
    cudaGetSymbolAddress(&cntp, g_cnt);
    cudaMemsetAsync(cntp, 0, N_NODES * sizeof(int));

    init_kernel<<<64, 256>>>(ei, W);
    hist_kernel<<<(N_EDGES / 4 + 255) / 256, 256>>>(ei);
    scan_kernel<<<1, 1024>>>();
    gemm_scatter_kernel<<<GEMM_BLOCKS + SCAT_BLOCKS, 256>>>(x, ei, a);
    gather_kernel<<<(N_NODES + 7) / 8, 256>>>(out);
}

// round 8
// speedup vs baseline: 1.5675x; 1.0002x over previous
#include <cuda_runtime.h>
#include <cuda_fp16.h>
#include <stdint.h>

#define N_NODES  50000
#define N_EDGES  1600000
#define IN_F     128
#define OUT_F    128
#define HEADS    4
#define HEAD_DIM 32
#define NEG_SLOPE 0.2f

#define GEMM_BM     64
#define GEMM_BLOCKS 782             // ceil(50000/64)
#define SCAT_BLOCKS 3125            // 1.6M edges / (256 thr * 2 edges)

// ---------------- device scratch ----------------
__device__ __half2 g_h2[N_NODES * (OUT_F / 2)];  // h as half2 (12.8 MB)
__device__ float   g_as[N_NODES * HEADS];
__device__ float   g_ad[N_NODES * HEADS];
__device__ float   g_Wt[IN_F * OUT_F];           // W transposed: g_Wt[k*128+c]
__device__ int     g_cnt[N_NODES];
__device__ int     g_off[N_NODES + 1];
__device__ int     g_cur[N_NODES];
__device__ int     g_srcs[N_EDGES];
__device__ int     g_is64;

// ---------------- init: dtype detect + W transpose ------------------------
__global__ __launch_bounds__(256) void init_kernel(
    const int* __restrict__ ei, const float* __restrict__ W)
{
    int lin = blockIdx.x * 256 + threadIdx.x;    // 64 blocks * 256 = 16384
    int c = lin >> 7, k = lin & 127;
    g_Wt[k * OUT_F + c] = W[c * IN_F + k];
    if (lin == 0) {
        int allzero = 1;
        #pragma unroll 1
        for (int i2 = 1; i2 < 256; i2 += 2)
            if (ei[i2] != 0) { allzero = 0; break; }
        g_is64 = allzero;
    }
}

// ---------------- histogram of dst (4 edges/thread) -----------------------
__global__ __launch_bounds__(256) void hist_kernel(const int* __restrict__ ei32) {
    const int e4 = (blockIdx.x * blockDim.x + threadIdx.x) * 4;
    if (e4 >= N_EDGES) return;
    int d0, d1, d2, d3;
    if (g_is64) {
        const longlong2* p = (const longlong2*)((const long long*)ei32 + N_EDGES + e4);
        longlong2 a = p[0], b = p[1];
        d0 = (int)a.x; d1 = (int)a.y; d2 = (int)b.x; d3 = (int)b.y;
    } else {
        int4 d = *(const int4*)(ei32 + N_EDGES + e4);
        d0 = d.x; d1 = d.y; d2 = d.z; d3 = d.w;
    }
    atomicAdd(&g_cnt[d0], 1);
    atomicAdd(&g_cnt[d1], 1);
    atomicAdd(&g_cnt[d2], 1);
    atomicAdd(&g_cnt[d3], 1);
}

// ---------------- single-CTA warp-shuffle scan ----------------------------
__global__ __launch_bounds__(1024) void scan_kernel() {
    __shared__ int warp_tot[32];
    const int t = threadIdx.x;
    const int lane = t & 31, wid = t >> 5;
    const int CH = (N_NODES + 1023) / 1024;      // 49
    const int base = t * CH;
    const unsigned m = 0xffffffffu;

    int sum = 0;
    #pragma unroll 1
    for (int i = 0; i < CH; i++) {
        int idx = base + i;
        if (idx < N_NODES) sum += g_cnt[idx];
    }
    int v = sum;
    #pragma unroll
    for (int off = 1; off < 32; off <<= 1) {
        int u = __shfl_up_sync(m, v, off);
        if (lane >= off) v += u;
    }
    if (lane == 31) warp_tot[wid] = v;
    __syncthreads();
    if (wid == 0) {
        int w = warp_tot[lane];
        #pragma unroll
        for (int off = 1; off < 32; off <<= 1) {
            int u = __shfl_up_sync(m, w, off);
            if (lane >= off) w += u;
        }
        warp_tot[lane] = w;
    }
    __syncthreads();
    int run = (v - sum) + (wid > 0 ? warp_tot[wid - 1] : 0);
    #pragma unroll 1
    for (int i = 0; i < CH; i++) {
        int idx = base + i;
        if (idx < N_NODES) {
            g_off[idx] = run;
            g_cur[idx] = run;
            run += g_cnt[idx];
        }
    }
    if (t == 1023) g_off[N_NODES] = run;
}

// ---------------- fused GEMM (h = x@W^T + alpha) || scatter ----------------
// GEMM blocks: 256 thr, 64 rows x 128 cols. Warp ty owns rows ty*8..+7;
// lane tx owns cols 4tx..4tx+3 (all in head tx>>3 -> 8-lane alpha reduce).
__global__ __launch_bounds__(256) void gemm_scatter_kernel(
    const float* __restrict__ x,
    const int*   __restrict__ ei32,
    const float* __restrict__ a)
{
    __shared__ float xs[GEMM_BM][IN_F + 4];

    if (blockIdx.x >= GEMM_BLOCKS) {
        // ---- scatter path: 2 edges per thread ----
        const int e = (blockIdx.x - GEMM_BLOCKS) * 512 + threadIdx.x * 2;
        int s0, s1, d0, d1;
        if (g_is64) {
            const long long* ei = (const long long*)ei32;
            longlong2 sv = *(const longlong2*)(ei + e);
            longlong2 dv = *(const longlong2*)(ei + N_EDGES + e);
            s0 = (int)sv.x; s1 = (int)sv.y; d0 = (int)dv.x; d1 = (int)dv.y;
        } else {
            int2 sv = *(const int2*)(ei32 + e);
            int2 dv = *(const int2*)(ei32 + N_EDGES + e);
            s0 = sv.x; s1 = sv.y; d0 = dv.x; d1 = dv.y;
        }
        int p0 = atomicAdd(&g_cur[d0], 1);
        g_srcs[p0] = s0;
        int p1 = atomicAdd(&g_cur[d1], 1);
        g_srcs[p1] = s1;
        return;
    }

    // ---- GEMM path ----
    const int t  = threadIdx.x;
    const int tx = t & 31;
    const int ty = t >> 5;
    const int rowbase = blockIdx.x * GEMM_BM;

    for (int f = t; f < GEMM_BM * 32; f += 256) {
        int mm = f >> 5, k4 = f & 31;
        int row = rowbase + mm;
        float4 v = make_float4(0.f, 0.f, 0.f, 0.f);
        if (row < N_NODES) v = *(const float4*)(x + (size_t)row * IN_F + k4 * 4);
        *(float4*)&xs[mm][k4 * 4] = v;
    }
    __syncthreads();

    float acc[8][4];
    #pragma unroll
    for (int i = 0; i < 8; i++)
        #pragma unroll
        for (int j = 0; j < 4; j++) acc[i][j] = 0.f;

    const float4* wt4 = (const float4*)g_Wt;
    const int m0 = ty * 8;

    #pragma unroll 2
    for (int k = 0; k < IN_F; k += 4) {
        float4 wr[4];
        #pragma unroll
        for (int q = 0; q < 4; q++)
            wr[q] = wt4[(k + q) * 32 + tx];
        #pragma unroll
        for (int i = 0; i < 8; i++) {
            float4 xv = *(const float4*)&xs[m0 + i][k];   // broadcast LDS.128
            acc[i][0] = fmaf(xv.x, wr[0].x, acc[i][0]);
            acc[i][1] = fmaf(xv.x, wr[0].y, acc[i][1]);
            acc[i][2] = fmaf(xv.x, wr[0].z, acc[i][2]);
            acc[i][3] = fmaf(xv.x, wr[0].w, acc[i][3]);
            acc[i][0] = fmaf(xv.y, wr[1].x, acc[i][0]);
            acc[i][1] = fmaf(xv.y, wr[1].y, acc[i][1]);
            acc[i][2] = fmaf(xv.y, wr[1].z, acc[i][2]);
            acc[i][3] = fmaf(xv.y, wr[1].w, acc[i][3]);
            acc[i][0] = fmaf(xv.z, wr[2].x, acc[i][0]);
            acc[i][1] = fmaf(xv.z, wr[2].y, acc[i][1]);
            acc[i][2] = fmaf(xv.z, wr[2].z, acc[i][2]);
            acc[i][3] = fmaf(xv.z, wr[2].w, acc[i][3]);
            acc[i][0] = fmaf(xv.w, wr[3].x, acc[i][0]);
            acc[i][1] = fmaf(xv.w, wr[3].y, acc[i][1]);
            acc[i][2] = fmaf(xv.w, wr[3].z, acc[i][2]);
            acc[i][3] = fmaf(xv.w, wr[3].w, acc[i][3]);
        }
    }

    // epilogue: h -> half2, fused alpha reductions (8-lane segmented)
    const int head = tx >> 3;
    const int d0c  = (tx & 7) * 4;
    float as_v[4], ad_v[4];
    #pragma unroll
    for (int j = 0; j < 4; j++) {
        as_v[j] = a[head * 2 * HEAD_DIM + d0c + j];
        ad_v[j] = a[head * 2 * HEAD_DIM + HEAD_DIM + d0c + j];
    }
    const unsigned msk = 0xffffffffu;

    #pragma unroll
    for (int i = 0; i < 8; i++) {
        const int row = rowbase + m0 + i;
        if (row >= N_NODES) break;
        __half2 p0 = __floats2half2_rn(acc[i][0], acc[i][1]);
        __half2 p1 = __floats2half2_rn(acc[i][2], acc[i][3]);
        uint2 u;
        u.x = *(const unsigned*)&p0;
        u.y = *(const unsigned*)&p1;
        *(uint2*)&g_h2[(size_t)row * 64 + tx * 2] = u;

        float s = acc[i][0] * as_v[0] + acc[i][1] * as_v[1]
                + acc[i][2] * as_v[2] + acc[i][3] * as_v[3];
        float d = acc[i][0] * ad_v[0] + acc[i][1] * ad_v[1]
                + acc[i][2] * ad_v[2] + acc[i][3] * ad_v[3];
        #pragma unroll
        for (int off = 1; off < 8; off <<= 1) {
            s += __shfl_xor_sync(msk, s, off);
            d += __shfl_xor_sync(msk, d, off);
        }
        if ((tx & 7) == 0) {
            g_as[row * HEADS + head] = s;
            g_ad[row * HEADS + head] = d;
        }
    }
}

// ---------------- gather: warp per node, half-warp per edge ---------------
// Lanes 0-15 process edge e, lanes 16-31 edge e+1. Each lane owns 8
// contiguous features (one head) -> per-lane independent att, no shuffles
// in the loop. Final combine: shfl_xor(16).
__device__ __forceinline__ float leaky(float v) {
    return (v > 0.f) ? v : NEG_SLOPE * v;
}

__global__ __launch_bounds__(256) void gather_kernel(float* __restrict__ out) {
    const int n = blockIdx.x * 8 + (threadIdx.x >> 5);
    if (n >= N_NODES) return;
    const int lane = threadIdx.x & 31;
    const int hw = lane >> 4;          // which edge of the pair
    const int sl = lane & 15;          // feature-group owner: halfs 8sl..8sl+7
    const int h  = sl >> 2;            // head of those features
    const float myad = g_ad[n * HEADS + h];

    float acc[8];
    #pragma unroll
    for (int j = 0; j < 8; j++) acc[j] = 0.f;

    const int start = g_off[n];
    const int end   = g_off[n + 1];
    int e = start;

    #pragma unroll 1
    for (; e + 4 <= end; e += 4) {
        #pragma unroll
        for (int p = 0; p < 2; p++) {
            const int s = g_srcs[e + 2 * p + hw];
            const float att = leaky(g_as[s * HEADS + h] + myad);
            const uint4 u = *(const uint4*)&g_h2[(size_t)s * 64 + sl * 4];
            float2 f;
            f = __half22float2(*(const __half2*)&u.x);
            acc[0] = fmaf(att, f.x, acc[0]); acc[1] = fmaf(att, f.y, acc[1]);
            f = __half22float2(*(const __half2*)&u.y);
            acc[2] = fmaf(att, f.x, acc[2]); acc[3] = fmaf(att, f.y, acc[3]);
            f = __half22float2(*(const __half2*)&u.z);
            acc[4] = fmaf(att, f.x, acc[4]); acc[5] = fmaf(att, f.y, acc[5]);
            f = __half22float2(*(const __half2*)&u.w);
            acc[6] = fmaf(att, f.x, acc[6]); acc[7] = fmaf(att, f.y, acc[7]);
        }
    }
    #pragma unroll 1
    for (; e < end; e += 2) {
        if (e + hw < end) {
            const int s = g_srcs[e + hw];
            const float att = leaky(g_as[s * HEADS + h] + myad);
            const uint4 u = *(const uint4*)&g_h2[(size_t)s * 64 + sl * 4];
            float2 f;
            f = __half22float2(*(const __half2*)&u.x);
            acc[0] = fmaf(att, f.x, acc[0]); acc[1] = fmaf(att, f.y, acc[1]);
            f = __half22float2(*(const __half2*)&u.y);
            acc[2] = fmaf(att, f.x, acc[2]); acc[3] = fmaf(att, f.y, acc[3]);
            f = __half22float2(*(const __half2*)&u.z);
            acc[4] = fmaf(att, f.x, acc[4]); acc[5] = fmaf(att, f.y, acc[5]);
            f = __half22float2(*(const __half2*)&u.w);
            acc[6] = fmaf(att, f.x, acc[6]); acc[7] = fmaf(att, f.y, acc[7]);
        }
    }

    // combine the two half-warps
    const unsigned msk = 0xffffffffu;
    #pragma unroll
    for (int j = 0; j < 8; j++)
        acc[j] += __shfl_xor_sync(msk, acc[j], 16);

    float* op = out + (size_t)n * OUT_F + sl * 8;
    if (hw == 0)
        *(float4*)op = make_float4(acc[0], acc[1], acc[2], acc[3]);
    else
        *(float4*)(op + 4) = make_float4(acc[4], acc[5], acc[6], acc[7]);
}

// ---------------- launch -------------------------------------------------
extern "C" void kernel_launch(void* const* d_in, const int* in_sizes, int n_in,
                              void* d_out, int out_size) {
    const float* x  = (const float*)d_in[0];
    const int*   ei = (const int*)d_in[1];
    const float* W  = (const float*)d_in[2];
    const float* a  = (const float*)d_in[3];
    float* out = (float*)d_out;

    void* cntp = nullptr;
    cudaGetSymbolAddress(&cntp, g_cnt);
    cudaMemsetAsync(cntp, 0, N_NODES * sizeof(int));

    init_kernel<<<64, 256>>>(ei, W);
    hist_kernel<<<(N_EDGES / 4 + 255) / 256, 256>>>(ei);
    scan_kernel<<<1, 1024>>>();
    gemm_scatter_kernel<<<GEMM_BLOCKS + SCAT_BLOCKS, 256>>>(x, ei, a);
    gather_kernel<<<(N_NODES + 7) / 8, 256>>>(out);
}

// round 9
// speedup vs baseline: 2.3396x; 1.4925x over previous
#include <cuda_runtime.h>
#include <cuda_fp16.h>
#include <stdint.h>

#define N_NODES  50000
#define N_EDGES  1600000
#define IN_F     128
#define OUT_F    128
#define HEADS    4
#define HEAD_DIM 32
#define NEG_SLOPE 0.2f

#define GEMM_BM     64
#define GEMM_BLOCKS 782             // ceil(50000/64)
#define SCAT_BLOCKS 3125            // 1.6M edges / (128 thr * 4 edges)

// ---------------- device scratch ----------------
__device__ __half2 g_h2[N_NODES * (OUT_F / 2)];  // h as half2 (12.8 MB)
__device__ float   g_as[N_NODES * HEADS];
__device__ float   g_ad[N_NODES * HEADS];
__device__ uint4   g_Wf[2048];                   // W in mma B-fragment layout (32KB)
__device__ int     g_cnt[N_NODES];
__device__ int     g_off[N_NODES + 1];
__device__ int     g_cur[N_NODES];
__device__ int     g_srcs[N_EDGES];
__device__ int     g_is64;

// ---------------- init: dtype detect + W fragment packing ----------------
// g_Wf[(ks*8 + j)*32 + lane] = uint4{ b0(n=2j), b1(n=2j), b0(n=2j+1), b1(n=2j+1) }
// where for m16n8k16.col B frag: b0 = half2(Wt[k0][col], Wt[k0+1][col]),
// b1 = half2(Wt[k0+8][col], Wt[k0+9][col]); col = n*8 + lane/4,
// k0 = ks*16 + (lane%4)*2; Wt[k][c] = W[c*IN_F + k].
__global__ __launch_bounds__(256) void init_kernel(
    const int* __restrict__ ei, const float* __restrict__ W)
{
    const int L = blockIdx.x * 256 + threadIdx.x;   // 8 blocks * 256 = 2048
    const int lane = L & 31;
    const int j    = (L >> 5) & 7;
    const int ks   = L >> 8;
    const int k0   = ks * 16 + (lane & 3) * 2;

    uint4 q;
    #pragma unroll
    for (int p = 0; p < 2; p++) {
        const int col = (2 * j + p) * 8 + (lane >> 2);
        const float* wr = W + col * IN_F;
        __half2 b0 = __floats2half2_rn(wr[k0],     wr[k0 + 1]);
        __half2 b1 = __floats2half2_rn(wr[k0 + 8], wr[k0 + 9]);
        if (p == 0) { q.x = *(const unsigned*)&b0; q.y = *(const unsigned*)&b1; }
        else        { q.z = *(const unsigned*)&b0; q.w = *(const unsigned*)&b1; }
    }
    g_Wf[L] = q;

    if (L == 0) {
        int allzero = 1;
        #pragma unroll 1
        for (int i2 = 1; i2 < 256; i2 += 2)
            if (ei[i2] != 0) { allzero = 0; break; }
        g_is64 = allzero;
    }
}

// ---------------- histogram of dst (4 edges/thread) -----------------------
__global__ __launch_bounds__(256) void hist_kernel(const int* __restrict__ ei32) {
    const int e4 = (blockIdx.x * blockDim.x + threadIdx.x) * 4;
    if (e4 >= N_EDGES) return;
    int d0, d1, d2, d3;
    if (g_is64) {
        const longlong2* p = (const longlong2*)((const long long*)ei32 + N_EDGES + e4);
        longlong2 a = p[0], b = p[1];
        d0 = (int)a.x; d1 = (int)a.y; d2 = (int)b.x; d3 = (int)b.y;
    } else {
        int4 d = *(const int4*)(ei32 + N_EDGES + e4);
        d0 = d.x; d1 = d.y; d2 = d.z; d3 = d.w;
    }
    atomicAdd(&g_cnt[d0], 1);
    atomicAdd(&g_cnt[d1], 1);
    atomicAdd(&g_cnt[d2], 1);
    atomicAdd(&g_cnt[d3], 1);
}

// ---------------- single-CTA scan, coalesced 1024-rounds ------------------
__global__ __launch_bounds__(1024) void scan_kernel() {
    __shared__ int wtot[32];
    const int t = threadIdx.x;
    const int lane = t & 31, wid = t >> 5;
    const unsigned m = 0xffffffffu;
    int base = 0;

    #pragma unroll 1
    for (int i = 0; i < (N_NODES + 1023) / 1024; i++) {
        const int idx = i * 1024 + t;
        const int v = (idx < N_NODES) ? g_cnt[idx] : 0;
        int incl = v;
        #pragma unroll
        for (int off = 1; off < 32; off <<= 1) {
            int u = __shfl_up_sync(m, incl, off);
            if (lane >= off) incl += u;
        }
        if (lane == 31) wtot[wid] = incl;
        __syncthreads();
        if (wid == 0) {
            int w2 = wtot[lane];
            #pragma unroll
            for (int off = 1; off < 32; off <<= 1) {
                int u = __shfl_up_sync(m, w2, off);
                if (lane >= off) w2 += u;
            }
            wtot[lane] = w2;
        }
        __syncthreads();
        const int excl = incl - v + (wid ? wtot[wid - 1] : 0) + base;
        if (idx < N_NODES) { g_off[idx] = excl; g_cur[idx] = excl; }
        base += wtot[31];
        __syncthreads();
    }
    if (t == 0) g_off[N_NODES] = base;
}

// ---------------- fused tensor-core GEMM || scatter ------------------------
// GEMM blocks: 128 thr = 4 warps; CTA = 64 rows x 128 cols.
// Warp w: rows rowbase + w*16 + {lane/4, lane/4+8}; 16 n-tiles of 8 cols.
__device__ __forceinline__ void mma16816(
    float* c, unsigned a0, unsigned a1, unsigned a2, unsigned a3,
    unsigned b0, unsigned b1)
{
    asm volatile(
        "mma.sync.aligned.m16n8k16.row.col.f32.f16.f16.f32 "
        "{%0,%1,%2,%3}, {%4,%5,%6,%7}, {%8,%9}, {%0,%1,%2,%3};"
        : "+f"(c[0]), "+f"(c[1]), "+f"(c[2]), "+f"(c[3])
        : "r"(a0), "r"(a1), "r"(a2), "r"(a3), "r"(b0), "r"(b1));
}

__global__ __launch_bounds__(128) void gemm_scatter_kernel(
    const float* __restrict__ x,
    const int*   __restrict__ ei32,
    const float* __restrict__ a)
{
    __shared__ __half xh[GEMM_BM][IN_F + 8];

    if (blockIdx.x >= GEMM_BLOCKS) {
        // ---- scatter path: 4 edges per thread ----
        const int e = (blockIdx.x - GEMM_BLOCKS) * 512 + threadIdx.x * 4;
        int s[4], d[4];
        if (g_is64) {
            const long long* ei = (const long long*)ei32;
            const longlong2* sp = (const longlong2*)(ei + e);
            const longlong2* dp = (const longlong2*)(ei + N_EDGES + e);
            longlong2 s01 = sp[0], s23 = sp[1], d01 = dp[0], d23 = dp[1];
            s[0] = (int)s01.x; s[1] = (int)s01.y; s[2] = (int)s23.x; s[3] = (int)s23.y;
            d[0] = (int)d01.x; d[1] = (int)d01.y; d[2] = (int)d23.x; d[3] = (int)d23.y;
        } else {
            int4 sv = *(const int4*)(ei32 + e);
            int4 dv = *(const int4*)(ei32 + N_EDGES + e);
            s[0] = sv.x; s[1] = sv.y; s[2] = sv.z; s[3] = sv.w;
            d[0] = dv.x; d[1] = dv.y; d[2] = dv.z; d[3] = dv.w;
        }
        #pragma unroll
        for (int p = 0; p < 4; p++) {
            int pos = atomicAdd(&g_cur[d[p]], 1);
            g_srcs[pos] = s[p];
        }
        return;
    }

    // ---- GEMM path ----
    const int t    = threadIdx.x;
    const int lane = t & 31;
    const int w    = t >> 5;
    const int rowbase = blockIdx.x * GEMM_BM;

    // stage x tile as half (coalesced float4 reads)
    for (int f4 = t; f4 < GEMM_BM * 32; f4 += 128) {
        const int row = f4 >> 5, c4 = f4 & 31;
        const int grow = rowbase + row;
        float4 v = make_float4(0.f, 0.f, 0.f, 0.f);
        if (grow < N_NODES) v = *(const float4*)(x + (size_t)grow * IN_F + c4 * 4);
        __half2 h0 = __floats2half2_rn(v.x, v.y);
        __half2 h1 = __floats2half2_rn(v.z, v.w);
        uint2 u;
        u.x = *(const unsigned*)&h0;
        u.y = *(const unsigned*)&h1;
        *(uint2*)&xh[row][c4 * 4] = u;
    }
    __syncthreads();

    float acc[16][4];
    #pragma unroll
    for (int n = 0; n < 16; n++)
        #pragma unroll
        for (int q = 0; q < 4; q++) acc[n][q] = 0.f;

    const int sr = w * 16 + (lane >> 2);
    const int cc = (lane & 3) * 2;

    #pragma unroll
    for (int ks = 0; ks < 8; ks++) {
        const int kb = ks * 16;
        const unsigned a0 = *(const unsigned*)&xh[sr][kb + cc];
        const unsigned a1 = *(const unsigned*)&xh[sr + 8][kb + cc];
        const unsigned a2 = *(const unsigned*)&xh[sr][kb + cc + 8];
        const unsigned a3 = *(const unsigned*)&xh[sr + 8][kb + cc + 8];
        #pragma unroll
        for (int j = 0; j < 8; j++) {
            const uint4 q = g_Wf[(ks * 8 + j) * 32 + lane];
            mma16816(acc[2 * j],     a0, a1, a2, a3, q.x, q.y);
            mma16816(acc[2 * j + 1], a0, a1, a2, a3, q.z, q.w);
        }
    }

    // epilogue: h -> half2 store + fused alpha reductions
    const int cq = lane & 3;
    const unsigned msk = 0xffffffffu;

    #pragma unroll
    for (int rh = 0; rh < 2; rh++) {
        const int row = rowbase + w * 16 + (lane >> 2) + rh * 8;
        const bool valid = (row < N_NODES);
        float ps[4] = {0.f, 0.f, 0.f, 0.f};
        float pd[4] = {0.f, 0.f, 0.f, 0.f};

        #pragma unroll
        for (int n = 0; n < 16; n++) {
            const float c0 = acc[n][rh * 2];
            const float c1 = acc[n][rh * 2 + 1];
            if (valid) {
                __half2 hp = __floats2half2_rn(c0, c1);
                ((unsigned*)g_h2)[(size_t)row * 64 + n * 4 + cq] = *(const unsigned*)&hp;
            }
            const int head = n >> 2;
            const int wc   = (n & 3) * 8 + cq * 2;        // within-head col
            const float2 asv = *(const float2*)&a[head * 64 + wc];
            const float2 adv = *(const float2*)&a[head * 64 + 32 + wc];
            ps[head] += c0 * asv.x + c1 * asv.y;
            pd[head] += c0 * adv.x + c1 * adv.y;
        }
        #pragma unroll
        for (int h = 0; h < 4; h++) {
            ps[h] += __shfl_xor_sync(msk, ps[h], 1);
            ps[h] += __shfl_xor_sync(msk, ps[h], 2);
            pd[h] += __shfl_xor_sync(msk, pd[h], 1);
            pd[h] += __shfl_xor_sync(msk, pd[h], 2);
        }
        if (valid) {
            g_as[row * HEADS + cq] = ps[cq];   // lane cq of the quad owns head cq
            g_ad[row * HEADS + cq] = pd[cq];
        }
    }
}

// ---------------- gather: warp per node, half-warp per edge ---------------
__device__ __forceinline__ float leaky(float v) {
    return (v > 0.f) ? v : NEG_SLOPE * v;
}

__global__ __launch_bounds__(256) void gather_kernel(float* __restrict__ out) {
    const int n = blockIdx.x * 8 + (threadIdx.x >> 5);
    if (n >= N_NODES) return;
    const int lane = threadIdx.x & 31;
    const int hw = lane >> 4;
    const int sl = lane & 15;
    const int h  = sl >> 2;
    const float myad = g_ad[n * HEADS + h];

    float acc[8];
    #pragma unroll
    for (int j = 0; j < 8; j++) acc[j] = 0.f;

    const int start = g_off[n];
    const int end   = g_off[n + 1];
    int e = start;

    #pragma unroll 1
    for (; e + 4 <= end; e += 4) {
        #pragma unroll
        for (int p = 0; p < 2; p++) {
            const int s = g_srcs[e + 2 * p + hw];
            const float att = leaky(g_as[s * HEADS + h] + myad);
            const uint4 u = *(const uint4*)&g_h2[(size_t)s * 64 + sl * 4];
            float2 f;
            f = __half22float2(*(const __half2*)&u.x);
            acc[0] = fmaf(att, f.x, acc[0]); acc[1] = fmaf(att, f.y, acc[1]);
            f = __half22float2(*(const __half2*)&u.y);
            acc[2] = fmaf(att, f.x, acc[2]); acc[3] = fmaf(att, f.y, acc[3]);
            f = __half22float2(*(const __half2*)&u.z);
            acc[4] = fmaf(att, f.x, acc[4]); acc[5] = fmaf(att, f.y, acc[5]);
            f = __half22float2(*(const __half2*)&u.w);
            acc[6] = fmaf(att, f.x, acc[6]); acc[7] = fmaf(att, f.y, acc[7]);
        }
    }
    #pragma unroll 1
    for (; e < end; e += 2) {
        if (e + hw < end) {
            const int s = g_srcs[e + hw];
            const float att = leaky(g_as[s * HEADS + h] + myad);
            const uint4 u = *(const uint4*)&g_h2[(size_t)s * 64 + sl * 4];
            float2 f;
            f = __half22float2(*(const __half2*)&u.x);
            acc[0] = fmaf(att, f.x, acc[0]); acc[1] = fmaf(att, f.y, acc[1]);
            f = __half22float2(*(const __half2*)&u.y);
            acc[2] = fmaf(att, f.x, acc[2]); acc[3] = fmaf(att, f.y, acc[3]);
            f = __half22float2(*(const __half2*)&u.z);
            acc[4] = fmaf(att, f.x, acc[4]); acc[5] = fmaf(att, f.y, acc[5]);
            f = __half22float2(*(const __half2*)&u.w);
            acc[6] = fmaf(att, f.x, acc[6]); acc[7] = fmaf(att, f.y, acc[7]);
        }
    }

    const unsigned msk = 0xffffffffu;
    #pragma unroll
    for (int j = 0; j < 8; j++)
        acc[j] += __shfl_xor_sync(msk, acc[j], 16);

    float* op = out + (size_t)n * OUT_F + sl * 8;
    if (hw == 0)
        *(float4*)op = make_float4(acc[0], acc[1], acc[2], acc[3]);
    else
        *(float4*)(op + 4) = make_float4(acc[4], acc[5], acc[6], acc[7]);
}

// ---------------- launch -------------------------------------------------
extern "C" void kernel_launch(void* const* d_in, const int* in_sizes, int n_in,
                              void* d_out, int out_size) {
    const float* x  = (const float*)d_in[0];
    const int*   ei = (const int*)d_in[1];
    const float* W  = (const float*)d_in[2];
    const float* a  = (const float*)d_in[3];
    float* out = (float*)d_out;

    void* cntp = nullptr;
    cudaGetSymbolAddress(&cntp, g_cnt);
    cudaMemsetAsync(cntp, 0, N_NODES * sizeof(int));

    init_kernel<<<8, 256>>>(ei, W);
    hist_kernel<<<(N_EDGES / 4 + 255) / 256, 256>>>(ei);
    scan_kernel<<<1, 1024>>>();
    gemm_scatter_kernel<<<GEMM_BLOCKS + SCAT_BLOCKS, 128>>>(x, ei, a);
    gather_kernel<<<(N_NODES + 7) / 8, 256>>>(out);
}